// round 1
// baseline (speedup 1.0000x reference)
#include <cuda_runtime.h>

#define BSZ 4
#define CS  1024
#define PS  1024
#define DIN 1024
#define H   16
#define D   64
#define T   2048
#define SCALEF 0.125f

// ---------------- scratch (static device globals; allocation-free) ----------
__device__ float g_kv [(size_t)BSZ * T * 2 * H * D];   // [b*T+t][2048]  k: cols 0..1023, v: cols 1024..2047
__device__ float g_q  [(size_t)BSZ * CS * H * D];      // [b*CS+i][1024]
__device__ float g_p  [(size_t)T * H * D];             // [j][1024]
__device__ float g_pa [(size_t)H * BSZ * CS * T];      // [h][M][j]  (pre-shift position scores)
__device__ float g_awv[(size_t)BSZ * CS * H * D];      // attention output before W_out

// ---------------- generic 128x128x8 SIMT fp32 GEMM --------------------------
// C[M,N] = A[M,K] @ B[K,N], all row-major. M%128==0, N%128==0, K%8==0.
__global__ __launch_bounds__(256, 2)
void gemm_plain(const float* __restrict__ A, const float* __restrict__ B,
                float* __restrict__ C, int M, int N, int K)
{
    __shared__ float As[8][128];
    __shared__ float Bs[8][128];
    int tid = threadIdx.x;
    int tx = tid & 15, ty = tid >> 4;
    int m0 = blockIdx.y * 128, n0 = blockIdx.x * 128;

    int lr = tid >> 1;            // A tile row 0..127
    int lc = (tid & 1) * 4;       // A tile col {0,4}
    int bk = tid >> 5;            // B tile row 0..7
    int bj = (tid & 31) * 4;      // B tile col

    float acc[8][8];
#pragma unroll
    for (int i = 0; i < 8; i++)
#pragma unroll
        for (int j = 0; j < 8; j++) acc[i][j] = 0.f;

    for (int k0 = 0; k0 < K; k0 += 8) {
        float4 av = *(const float4*)(A + (size_t)(m0 + lr) * K + k0 + lc);
        float4 bv = *(const float4*)(B + (size_t)(k0 + bk) * N + n0 + bj);
        As[lc + 0][lr] = av.x; As[lc + 1][lr] = av.y;
        As[lc + 2][lr] = av.z; As[lc + 3][lr] = av.w;
        *(float4*)&Bs[bk][bj] = bv;
        __syncthreads();
#pragma unroll
        for (int kk = 0; kk < 8; kk++) {
            float a[8], b[8];
            *(float4*)&a[0] = *(const float4*)&As[kk][ty * 8];
            *(float4*)&a[4] = *(const float4*)&As[kk][ty * 8 + 4];
            *(float4*)&b[0] = *(const float4*)&Bs[kk][tx * 8];
            *(float4*)&b[4] = *(const float4*)&Bs[kk][tx * 8 + 4];
#pragma unroll
            for (int i = 0; i < 8; i++)
#pragma unroll
                for (int j = 0; j < 8; j++) acc[i][j] += a[i] * b[j];
        }
        __syncthreads();
    }
#pragma unroll
    for (int i = 0; i < 8; i++) {
        float* Crow = C + (size_t)(m0 + ty * 8 + i) * N + n0 + tx * 8;
        *(float4*)Crow       = make_float4(acc[i][0], acc[i][1], acc[i][2], acc[i][3]);
        *(float4*)(Crow + 4) = make_float4(acc[i][4], acc[i][5], acc[i][6], acc[i][7]);
    }
}

// ---------------- kv GEMM: virtual A = concat(memory, input) per batch -----
// C = g_kv, M = BSZ*T = 8192, N = 2048, K = 1024
__global__ __launch_bounds__(256, 2)
void gemm_kv_kernel(const float* __restrict__ input, const float* __restrict__ memory,
                    const float* __restrict__ Wkv)
{
    const int N = 2 * H * D, K = DIN;
    __shared__ float As[8][128];
    __shared__ float Bs[8][128];
    int tid = threadIdx.x;
    int tx = tid & 15, ty = tid >> 4;
    int m0 = blockIdx.y * 128, n0 = blockIdx.x * 128;

    int lr = tid >> 1;
    int lc = (tid & 1) * 4;
    int bk = tid >> 5;
    int bj = (tid & 31) * 4;

    int grow = m0 + lr;
    int b = grow >> 11;          // T = 2048
    int t = grow & (T - 1);
    const float* Arow = (t < PS) ? (memory + (size_t)(b * PS + t) * DIN)
                                 : (input  + (size_t)(b * CS + (t - PS)) * DIN);

    float acc[8][8];
#pragma unroll
    for (int i = 0; i < 8; i++)
#pragma unroll
        for (int j = 0; j < 8; j++) acc[i][j] = 0.f;

    for (int k0 = 0; k0 < K; k0 += 8) {
        float4 av = *(const float4*)(Arow + k0 + lc);
        float4 bv = *(const float4*)(Wkv + (size_t)(k0 + bk) * N + n0 + bj);
        As[lc + 0][lr] = av.x; As[lc + 1][lr] = av.y;
        As[lc + 2][lr] = av.z; As[lc + 3][lr] = av.w;
        *(float4*)&Bs[bk][bj] = bv;
        __syncthreads();
#pragma unroll
        for (int kk = 0; kk < 8; kk++) {
            float a[8], bb[8];
            *(float4*)&a[0]  = *(const float4*)&As[kk][ty * 8];
            *(float4*)&a[4]  = *(const float4*)&As[kk][ty * 8 + 4];
            *(float4*)&bb[0] = *(const float4*)&Bs[kk][tx * 8];
            *(float4*)&bb[4] = *(const float4*)&Bs[kk][tx * 8 + 4];
#pragma unroll
            for (int i = 0; i < 8; i++)
#pragma unroll
                for (int j = 0; j < 8; j++) acc[i][j] += a[i] * bb[j];
        }
        __syncthreads();
    }
#pragma unroll
    for (int i = 0; i < 8; i++) {
        float* Crow = g_kv + (size_t)(m0 + ty * 8 + i) * N + n0 + tx * 8;
        *(float4*)Crow       = make_float4(acc[i][0], acc[i][1], acc[i][2], acc[i][3]);
        *(float4*)(Crow + 4) = make_float4(acc[i][4], acc[i][5], acc[i][6], acc[i][7]);
    }
}

// ---------------- position-attn GEMM (per head) -----------------------------
// g_pa[h][M][j] = sum_d (q[M, h*64+d] + v[h,d]) * p[j, h*64+d]
// grid: (N/128=16, M/128=32, H=16). K = 64.
__global__ __launch_bounds__(256, 2)
void gemm_pa_kernel(const float* __restrict__ vvec)
{
    __shared__ float As[8][128];
    __shared__ float Bs[8][128];
    int tid = threadIdx.x;
    int tx = tid & 15, ty = tid >> 4;
    int h  = blockIdx.z;
    int m0 = blockIdx.y * 128, n0 = blockIdx.x * 128;

    int lr = tid >> 1;
    int lc = (tid & 1) * 4;

    float acc[8][8];
#pragma unroll
    for (int i = 0; i < 8; i++)
#pragma unroll
        for (int j = 0; j < 8; j++) acc[i][j] = 0.f;

    for (int k0 = 0; k0 < D; k0 += 8) {
        float4 av = *(const float4*)(g_q + (size_t)(m0 + lr) * (H * D) + h * D + k0 + lc);
        float4 vv = *(const float4*)(vvec + h * D + k0 + lc);
        float4 bv = *(const float4*)(g_p + (size_t)(n0 + lr) * (H * D) + h * D + k0 + lc);
        As[lc + 0][lr] = av.x + vv.x; As[lc + 1][lr] = av.y + vv.y;
        As[lc + 2][lr] = av.z + vv.z; As[lc + 3][lr] = av.w + vv.w;
        Bs[lc + 0][lr] = bv.x; Bs[lc + 1][lr] = bv.y;
        Bs[lc + 2][lr] = bv.z; Bs[lc + 3][lr] = bv.w;
        __syncthreads();
#pragma unroll
        for (int kk = 0; kk < 8; kk++) {
            float a[8], bb[8];
            *(float4*)&a[0]  = *(const float4*)&As[kk][ty * 8];
            *(float4*)&a[4]  = *(const float4*)&As[kk][ty * 8 + 4];
            *(float4*)&bb[0] = *(const float4*)&Bs[kk][tx * 8];
            *(float4*)&bb[4] = *(const float4*)&Bs[kk][tx * 8 + 4];
#pragma unroll
            for (int i = 0; i < 8; i++)
#pragma unroll
                for (int j = 0; j < 8; j++) acc[i][j] += a[i] * bb[j];
        }
        __syncthreads();
    }
#pragma unroll
    for (int i = 0; i < 8; i++) {
        float* Crow = g_pa + ((size_t)h * (BSZ * CS) + m0 + ty * 8 + i) * T + n0 + tx * 8;
        *(float4*)Crow       = make_float4(acc[i][0], acc[i][1], acc[i][2], acc[i][3]);
        *(float4*)(Crow + 4) = make_float4(acc[i][4], acc[i][5], acc[i][6], acc[i][7]);
    }
}

// ---------------- fused flash attention with rel-shift gather ---------------
// grid: (CS/32, H, BSZ), 256 threads. Bq=32, Bk=32.
// thread (r = tid>>3, g = tid&7): row r, score cols c = g + 8*cc, out dims g*8..g*8+7
__global__ __launch_bounds__(256)
void attn_kernel(const float* __restrict__ u)
{
    __shared__ float qs[32][64];
    __shared__ float ks[32][68];
    __shared__ float vs[32][68];
    __shared__ float pr[32][33];

    int tid = threadIdx.x;
    int b = blockIdx.z, h = blockIdx.y;
    int q0 = blockIdx.x * 32;
    int r = tid >> 3, g = tid & 7;

    // load Q tile (+u)
#pragma unroll
    for (int l = 0; l < 2; l++) {
        int idx = tid + l * 256;           // 512 float4 = 32x64 floats
        int i = idx >> 4, d4 = (idx & 15) * 4;
        float4 qv = *(const float4*)(g_q + (size_t)(b * CS + q0 + i) * (H * D) + h * D + d4);
        float4 uv = *(const float4*)(u + h * D + d4);
        qv.x += uv.x; qv.y += uv.y; qv.z += uv.z; qv.w += uv.w;
        *(float4*)&qs[i][d4] = qv;
    }

    float m = -1e30f, lsum = 0.f;
    float o[8];
#pragma unroll
    for (int dd = 0; dd < 8; dd++) o[dd] = 0.f;

    int iq   = q0 + r;
    int Mrow = b * CS + iq;
    int nkeys = q0 + 32 + PS; if (nkeys > T) nkeys = T;   // causal: j <= i + PS
    int ntiles = (nkeys + 31) >> 5;

    for (int tt = 0; tt < ntiles; tt++) {
        int j0 = tt * 32;
        __syncthreads();                                   // protect ks/vs/pr reuse
#pragma unroll
        for (int l = 0; l < 2; l++) {
            int idx = tid + l * 256;
            int c = idx >> 4, d4 = (idx & 15) * 4;
            const float* kvrow = g_kv + (size_t)(b * T + j0 + c) * (2 * H * D) + h * D + d4;
            *(float4*)&ks[c][d4] = *(const float4*)(kvrow);
            *(float4*)&vs[c][d4] = *(const float4*)(kvrow + H * D);
        }
        __syncthreads();

        // content scores (4 per thread)
        float sc[4] = {0.f, 0.f, 0.f, 0.f};
#pragma unroll
        for (int d4 = 0; d4 < 16; d4++) {
            float4 qv = *(const float4*)&qs[r][d4 * 4];
#pragma unroll
            for (int cc = 0; cc < 4; cc++) {
                float4 kf = *(const float4*)&ks[g + cc * 8][d4 * 4];
                sc[cc] += qv.x * kf.x + qv.y * kf.y + qv.z * kf.z + qv.w * kf.w;
            }
        }
        // add rel-shifted position scores + mask + scale
#pragma unroll
        for (int cc = 0; cc < 4; cc++) {
            int c = g + cc * 8;
            int j = j0 + c;
            int sp = j + BSZ * CS - Mrow;          // in [1, 6143]
            int Mp = Mrow + sp / (T + 1);          // source row, <= BSZ*CS-1
            int jp = sp % (T + 1);
            float pos = (jp == 0) ? 0.f
                       : g_pa[((size_t)h * (BSZ * CS) + Mp) * T + (jp - 1)];
            float val = (sc[cc] + pos) * SCALEF;
            sc[cc] = (j <= iq + PS) ? val : -1e30f;
        }
        // online softmax (8 threads per row)
        float tmax = fmaxf(fmaxf(sc[0], sc[1]), fmaxf(sc[2], sc[3]));
        tmax = fmaxf(tmax, __shfl_xor_sync(0xffffffffu, tmax, 1));
        tmax = fmaxf(tmax, __shfl_xor_sync(0xffffffffu, tmax, 2));
        tmax = fmaxf(tmax, __shfl_xor_sync(0xffffffffu, tmax, 4));
        float newm = fmaxf(m, tmax);
        float corr = __expf(m - newm);
        float psum = 0.f;
#pragma unroll
        for (int cc = 0; cc < 4; cc++) {
            float pv = __expf(sc[cc] - newm);
            pr[r][g + cc * 8] = pv;
            psum += pv;
        }
        psum += __shfl_xor_sync(0xffffffffu, psum, 1);
        psum += __shfl_xor_sync(0xffffffffu, psum, 2);
        psum += __shfl_xor_sync(0xffffffffu, psum, 4);
        lsum = lsum * corr + psum;
        m = newm;
#pragma unroll
        for (int dd = 0; dd < 8; dd++) o[dd] *= corr;
        __syncthreads();
        // O += P @ V
#pragma unroll 4
        for (int c = 0; c < 32; c++) {
            float pv = pr[r][c];
            float4 v0 = *(const float4*)&vs[c][g * 8];
            float4 v1 = *(const float4*)&vs[c][g * 8 + 4];
            o[0] += pv * v0.x; o[1] += pv * v0.y; o[2] += pv * v0.z; o[3] += pv * v0.w;
            o[4] += pv * v1.x; o[5] += pv * v1.y; o[6] += pv * v1.z; o[7] += pv * v1.w;
        }
    }

    float inv = 1.f / lsum;
    float* orow = g_awv + (size_t)Mrow * (H * D) + h * D + g * 8;
    *(float4*)orow       = make_float4(o[0] * inv, o[1] * inv, o[2] * inv, o[3] * inv);
    *(float4*)(orow + 4) = make_float4(o[4] * inv, o[5] * inv, o[6] * inv, o[7] * inv);
}

// ---------------- launch -----------------------------------------------------
extern "C" void kernel_launch(void* const* d_in, const int* in_sizes, int n_in,
                              void* d_out, int out_size)
{
    const float* input  = (const float*)d_in[0];
    const float* pos    = (const float*)d_in[1];
    const float* memory = (const float*)d_in[2];
    const float* u      = (const float*)d_in[3];
    const float* v      = (const float*)d_in[4];
    const float* Wkv    = (const float*)d_in[5];
    const float* Wq     = (const float*)d_in[6];
    const float* Wp     = (const float*)d_in[7];
    const float* Wout   = (const float*)d_in[8];
    // d_in[9] = mask: recomputed analytically (j <= i + PS), not read.
    float* out = (float*)d_out;

    float *pq, *pp, *pawv;
    cudaGetSymbolAddress((void**)&pq,   g_q);
    cudaGetSymbolAddress((void**)&pp,   g_p);
    cudaGetSymbolAddress((void**)&pawv, g_awv);

    // kv = [memory; input] @ W_kv       (8192 x 2048 x 1024)
    gemm_kv_kernel<<<dim3(16, 64), 256>>>(input, memory, Wkv);
    // q = input @ W_q                   (4096 x 1024 x 1024)
    gemm_plain<<<dim3(8, 32), 256>>>(input, Wq, pq, BSZ * CS, H * D, DIN);
    // p = pos_embs @ W_p                (2048 x 1024 x 1024)
    gemm_plain<<<dim3(8, 16), 256>>>(pos, Wp, pp, T, H * D, DIN);
    // pos_attn per head                 (16 x 4096 x 2048 x 64)
    gemm_pa_kernel<<<dim3(16, 32, H), 256>>>(v);
    // fused flash attention with rel-shift gather
    attn_kernel<<<dim3(CS / 32, H, BSZ), 256>>>(u);
    // out = awv @ W_out                 (4096 x 1024 x 1024)
    gemm_plain<<<dim3(8, 32), 256>>>(pawv, Wout, out, BSZ * CS, DIN, H * D);
}

// round 2
// speedup vs baseline: 1.3409x; 1.3409x over previous
#include <cuda_runtime.h>
#include <cstdint>

#define BSZ 4
#define CS  1024
#define PS  1024
#define DIN 1024
#define H   16
#define D   64
#define T   2048
#define SCALEF 0.125f

// ---------------- scratch (static device globals; allocation-free) ----------
__device__ float g_kv [(size_t)BSZ * T * 2 * H * D];   // [b*T+t][2048]  k: 0..1023, v: 1024..2047
__device__ float g_q  [(size_t)BSZ * CS * H * D];      // [b*CS+i][1024]
__device__ float g_p  [(size_t)T * H * D];             // [j][1024]
__device__ float g_pa [(size_t)H * BSZ * CS * T];      // [h][M][j]  pre-shift position scores
__device__ float g_awv[(size_t)BSZ * CS * H * D];      // attention output before W_out

// ---------------- tf32 helpers ----------------------------------------------
__device__ __forceinline__ uint32_t f2tf(float x) {
    uint32_t u;
    asm("cvt.rna.tf32.f32 %0, %1;" : "=r"(u) : "f"(x));
    return u;
}

#define MMA_TF32(c, a, b) \
    asm volatile("mma.sync.aligned.m16n8k8.row.col.f32.tf32.tf32.f32 " \
                 "{%0,%1,%2,%3},{%4,%5,%6,%7},{%8,%9},{%0,%1,%2,%3};" \
                 : "+f"(c[0]), "+f"(c[1]), "+f"(c[2]), "+f"(c[3]) \
                 : "r"(a[0]), "r"(a[1]), "r"(a[2]), "r"(a[3]), "r"(b[0]), "r"(b[1]))

// smem layouts: As[m][k] 128x36 (banks (4m+k)%32 conflict-free for frag reads)
//               Bs[k][n]  32x136 (banks (8k+n)%32 conflict-free)
#define AS_LD 36
#define BS_LD 136

// One K-chunk (32) of compute for this warp. acc[mt][nt][4].
__device__ __forceinline__ void mma_chunk(float acc[4][4][4],
                                          const uint32_t* __restrict__ As,
                                          const uint32_t* __restrict__ Bs,
                                          int wm, int wn, int lane)
{
    int g = lane >> 2, t = lane & 3;
#pragma unroll
    for (int ks = 0; ks < 4; ks++) {
        uint32_t a[4][4];
#pragma unroll
        for (int mt = 0; mt < 4; mt++) {
            int row = wm * 64 + mt * 16 + g;
            int col = ks * 8 + t;
            a[mt][0] = As[row * AS_LD + col];
            a[mt][1] = As[(row + 8) * AS_LD + col];
            a[mt][2] = As[row * AS_LD + col + 4];
            a[mt][3] = As[(row + 8) * AS_LD + col + 4];
        }
        uint32_t b[4][2];
#pragma unroll
        for (int nt = 0; nt < 4; nt++) {
            int brow = ks * 8 + t;
            int bcol = wn * 32 + nt * 8 + g;
            b[nt][0] = Bs[brow * BS_LD + bcol];
            b[nt][1] = Bs[(brow + 4) * BS_LD + bcol];
        }
#pragma unroll
        for (int mt = 0; mt < 4; mt++)
#pragma unroll
            for (int nt = 0; nt < 4; nt++)
                MMA_TF32(acc[mt][nt], a[mt], b[nt]);
    }
}

__device__ __forceinline__ void store_C(float acc[4][4][4], float* C, int ldc,
                                        int m0, int n0, int wm, int wn, int lane)
{
    int g = lane >> 2, t = lane & 3;
#pragma unroll
    for (int mt = 0; mt < 4; mt++) {
#pragma unroll
        for (int nt = 0; nt < 4; nt++) {
            int row = m0 + wm * 64 + mt * 16 + g;
            int col = n0 + wn * 32 + nt * 8 + 2 * t;
            float2 v01 = make_float2(acc[mt][nt][0], acc[mt][nt][1]);
            float2 v23 = make_float2(acc[mt][nt][2], acc[mt][nt][3]);
            *(float2*)(C + (size_t)row * ldc + col) = v01;
            *(float2*)(C + (size_t)(row + 8) * ldc + col) = v23;
        }
    }
}

// stage A (plain row-major MxK) tile 128 x 32 at (m0, k0)
__device__ __forceinline__ void stage_A_plain(uint32_t* As, const float* __restrict__ A,
                                              int lda, int m0, int k0, int tid)
{
#pragma unroll
    for (int i = 0; i < 4; i++) {
        int idx = tid + i * 256;
        int m = idx >> 3, kq = (idx & 7) * 4;
        float4 v = *(const float4*)(A + (size_t)(m0 + m) * lda + k0 + kq);
        As[m * AS_LD + kq + 0] = f2tf(v.x);
        As[m * AS_LD + kq + 1] = f2tf(v.y);
        As[m * AS_LD + kq + 2] = f2tf(v.z);
        As[m * AS_LD + kq + 3] = f2tf(v.w);
    }
}

// stage B (row-major KxN, ld=ldb) tile 32 x 128 at (k0, n0)
__device__ __forceinline__ void stage_B_w(uint32_t* Bs, const float* __restrict__ B,
                                          int ldb, int k0, int n0, int tid)
{
#pragma unroll
    for (int i = 0; i < 4; i++) {
        int idx = tid + i * 256;
        int k = idx >> 5, n4 = (idx & 31) * 4;
        float4 v = *(const float4*)(B + (size_t)(k0 + k) * ldb + n0 + n4);
        Bs[k * BS_LD + n4 + 0] = f2tf(v.x);
        Bs[k * BS_LD + n4 + 1] = f2tf(v.y);
        Bs[k * BS_LD + n4 + 2] = f2tf(v.z);
        Bs[k * BS_LD + n4 + 3] = f2tf(v.w);
    }
}

// ---------------- plain GEMM: C = A @ B (tf32 tensor cores) -----------------
__global__ __launch_bounds__(256, 2)
void mm_plain_tf32(const float* __restrict__ A, const float* __restrict__ B,
                   float* __restrict__ C, int M, int N, int K)
{
    __shared__ uint32_t As[128 * AS_LD];
    __shared__ uint32_t Bs[32 * BS_LD];
    int tid = threadIdx.x, lane = tid & 31, w = tid >> 5;
    int wm = w >> 2, wn = w & 3;
    int m0 = blockIdx.y * 128, n0 = blockIdx.x * 128;

    float acc[4][4][4];
#pragma unroll
    for (int i = 0; i < 4; i++)
#pragma unroll
        for (int j = 0; j < 4; j++)
#pragma unroll
            for (int r = 0; r < 4; r++) acc[i][j][r] = 0.f;

    for (int k0 = 0; k0 < K; k0 += 32) {
        stage_A_plain(As, A, K, m0, k0, tid);
        stage_B_w(Bs, B, N, k0, n0, tid);
        __syncthreads();
        mma_chunk(acc, As, Bs, wm, wn, lane);
        __syncthreads();
    }
    store_C(acc, C, N, m0, n0, wm, wn, lane);
}

// ---------------- kv GEMM: A rows gathered from [memory; input] -------------
__global__ __launch_bounds__(256, 2)
void mm_kv_tf32(const float* __restrict__ input, const float* __restrict__ memory,
                const float* __restrict__ Wkv)
{
    const int N = 2 * H * D, K = DIN;
    __shared__ uint32_t As[128 * AS_LD];
    __shared__ uint32_t Bs[32 * BS_LD];
    int tid = threadIdx.x, lane = tid & 31, w = tid >> 5;
    int wm = w >> 2, wn = w & 3;
    int m0 = blockIdx.y * 128, n0 = blockIdx.x * 128;

    float acc[4][4][4];
#pragma unroll
    for (int i = 0; i < 4; i++)
#pragma unroll
        for (int j = 0; j < 4; j++)
#pragma unroll
            for (int r = 0; r < 4; r++) acc[i][j][r] = 0.f;

    for (int k0 = 0; k0 < K; k0 += 32) {
#pragma unroll
        for (int i = 0; i < 4; i++) {
            int idx = tid + i * 256;
            int m = idx >> 3, kq = (idx & 7) * 4;
            int grow = m0 + m;
            int b = grow >> 11;
            int tl = grow & (T - 1);
            const float* Arow = (tl < PS) ? (memory + (size_t)(b * PS + tl) * DIN)
                                          : (input + (size_t)(b * CS + (tl - PS)) * DIN);
            float4 v = *(const float4*)(Arow + k0 + kq);
            As[m * AS_LD + kq + 0] = f2tf(v.x);
            As[m * AS_LD + kq + 1] = f2tf(v.y);
            As[m * AS_LD + kq + 2] = f2tf(v.z);
            As[m * AS_LD + kq + 3] = f2tf(v.w);
        }
        stage_B_w(Bs, Wkv, N, k0, n0, tid);
        __syncthreads();
        mma_chunk(acc, As, Bs, wm, wn, lane);
        __syncthreads();
    }
    store_C(acc, g_kv, N, m0, n0, wm, wn, lane);
}

// ---------------- position-attn GEMM (per head) ------------------------------
// g_pa[h][M][j] = sum_d (g_q[M, h*64+d] + v[h,d]) * g_p[j, h*64+d];  K = 64
__global__ __launch_bounds__(256, 2)
void mm_pa_tf32(const float* __restrict__ vvec)
{
    __shared__ uint32_t As[128 * AS_LD];
    __shared__ uint32_t Bs[32 * BS_LD];
    int tid = threadIdx.x, lane = tid & 31, w = tid >> 5;
    int wm = w >> 2, wn = w & 3;
    int h = blockIdx.z;
    int m0 = blockIdx.y * 128, n0 = blockIdx.x * 128;

    float acc[4][4][4];
#pragma unroll
    for (int i = 0; i < 4; i++)
#pragma unroll
        for (int j = 0; j < 4; j++)
#pragma unroll
            for (int r = 0; r < 4; r++) acc[i][j][r] = 0.f;

    for (int k0 = 0; k0 < D; k0 += 32) {
        // A = g_q slice + v broadcast
#pragma unroll
        for (int i = 0; i < 4; i++) {
            int idx = tid + i * 256;
            int m = idx >> 3, kq = (idx & 7) * 4;
            float4 a = *(const float4*)(g_q + (size_t)(m0 + m) * (H * D) + h * D + k0 + kq);
            float4 vv = *(const float4*)(vvec + h * D + k0 + kq);
            As[m * AS_LD + kq + 0] = f2tf(a.x + vv.x);
            As[m * AS_LD + kq + 1] = f2tf(a.y + vv.y);
            As[m * AS_LD + kq + 2] = f2tf(a.z + vv.z);
            As[m * AS_LD + kq + 3] = f2tf(a.w + vv.w);
        }
        // B^T source: g_p rows are n (keys), cols are k.  Bs[k][n] = g_p[n0+n][h*64+k0+k]
#pragma unroll
        for (int i = 0; i < 4; i++) {
            int idx = tid + i * 256;
            int n = idx & 127, k4 = (idx >> 7) * 4;
            float4 s = *(const float4*)(g_p + (size_t)(n0 + n) * (H * D) + h * D + k0 + k4);
            Bs[(k4 + 0) * BS_LD + n] = f2tf(s.x);
            Bs[(k4 + 1) * BS_LD + n] = f2tf(s.y);
            Bs[(k4 + 2) * BS_LD + n] = f2tf(s.z);
            Bs[(k4 + 3) * BS_LD + n] = f2tf(s.w);
        }
        __syncthreads();
        mma_chunk(acc, As, Bs, wm, wn, lane);
        __syncthreads();
    }
    store_C(acc, g_pa + (size_t)h * (BSZ * CS) * T, T, m0, n0, wm, wn, lane);
}

// ---------------- fused flash attention with rel-shift gather ---------------
__global__ __launch_bounds__(256)
void attn_kernel(const float* __restrict__ u)
{
    __shared__ float qs[32][64];
    __shared__ float ks[32][68];
    __shared__ float vs[32][68];
    __shared__ float pr[32][33];

    int tid = threadIdx.x;
    int b = blockIdx.z, h = blockIdx.y;
    int q0 = blockIdx.x * 32;
    int r = tid >> 3, g = tid & 7;

#pragma unroll
    for (int l = 0; l < 2; l++) {
        int idx = tid + l * 256;
        int i = idx >> 4, d4 = (idx & 15) * 4;
        float4 qv = *(const float4*)(g_q + (size_t)(b * CS + q0 + i) * (H * D) + h * D + d4);
        float4 uv = *(const float4*)(u + h * D + d4);
        qv.x += uv.x; qv.y += uv.y; qv.z += uv.z; qv.w += uv.w;
        *(float4*)&qs[i][d4] = qv;
    }

    float m = -1e30f, lsum = 0.f;
    float o[8];
#pragma unroll
    for (int dd = 0; dd < 8; dd++) o[dd] = 0.f;

    int iq = q0 + r;
    int Mrow = b * CS + iq;
    int nkeys = q0 + 32 + PS; if (nkeys > T) nkeys = T;
    int ntiles = (nkeys + 31) >> 5;

    for (int tt = 0; tt < ntiles; tt++) {
        int j0 = tt * 32;
        __syncthreads();
#pragma unroll
        for (int l = 0; l < 2; l++) {
            int idx = tid + l * 256;
            int c = idx >> 4, d4 = (idx & 15) * 4;
            const float* kvrow = g_kv + (size_t)(b * T + j0 + c) * (2 * H * D) + h * D + d4;
            *(float4*)&ks[c][d4] = *(const float4*)(kvrow);
            *(float4*)&vs[c][d4] = *(const float4*)(kvrow + H * D);
        }
        __syncthreads();

        float sc[4] = {0.f, 0.f, 0.f, 0.f};
#pragma unroll
        for (int d4 = 0; d4 < 16; d4++) {
            float4 qv = *(const float4*)&qs[r][d4 * 4];
#pragma unroll
            for (int cc = 0; cc < 4; cc++) {
                float4 kf = *(const float4*)&ks[g + cc * 8][d4 * 4];
                sc[cc] += qv.x * kf.x + qv.y * kf.y + qv.z * kf.z + qv.w * kf.w;
            }
        }
#pragma unroll
        for (int cc = 0; cc < 4; cc++) {
            int c = g + cc * 8;
            int j = j0 + c;
            int sp = j + BSZ * CS - Mrow;               // in [1, 6143]
            int add = (sp >= (T + 1)) + (sp >= 2 * (T + 1));
            int Mp = Mrow + add;
            int jp = sp - add * (T + 1);
            float pos = (jp == 0) ? 0.f
                       : g_pa[((size_t)h * (BSZ * CS) + Mp) * T + (jp - 1)];
            float val = (sc[cc] + pos) * SCALEF;
            sc[cc] = (j <= iq + PS) ? val : -1e30f;
        }
        float tmax = fmaxf(fmaxf(sc[0], sc[1]), fmaxf(sc[2], sc[3]));
        tmax = fmaxf(tmax, __shfl_xor_sync(0xffffffffu, tmax, 1));
        tmax = fmaxf(tmax, __shfl_xor_sync(0xffffffffu, tmax, 2));
        tmax = fmaxf(tmax, __shfl_xor_sync(0xffffffffu, tmax, 4));
        float newm = fmaxf(m, tmax);
        float corr = __expf(m - newm);
        float psum = 0.f;
#pragma unroll
        for (int cc = 0; cc < 4; cc++) {
            float pv = __expf(sc[cc] - newm);
            pr[r][g + cc * 8] = pv;
            psum += pv;
        }
        psum += __shfl_xor_sync(0xffffffffu, psum, 1);
        psum += __shfl_xor_sync(0xffffffffu, psum, 2);
        psum += __shfl_xor_sync(0xffffffffu, psum, 4);
        lsum = lsum * corr + psum;
        m = newm;
#pragma unroll
        for (int dd = 0; dd < 8; dd++) o[dd] *= corr;
        __syncthreads();
#pragma unroll 4
        for (int c = 0; c < 32; c++) {
            float pv = pr[r][c];
            float4 v0 = *(const float4*)&vs[c][g * 8];
            float4 v1 = *(const float4*)&vs[c][g * 8 + 4];
            o[0] += pv * v0.x; o[1] += pv * v0.y; o[2] += pv * v0.z; o[3] += pv * v0.w;
            o[4] += pv * v1.x; o[5] += pv * v1.y; o[6] += pv * v1.z; o[7] += pv * v1.w;
        }
    }

    float inv = 1.f / lsum;
    float* orow = g_awv + (size_t)Mrow * (H * D) + h * D + g * 8;
    *(float4*)orow       = make_float4(o[0] * inv, o[1] * inv, o[2] * inv, o[3] * inv);
    *(float4*)(orow + 4) = make_float4(o[4] * inv, o[5] * inv, o[6] * inv, o[7] * inv);
}

// ---------------- launch -----------------------------------------------------
extern "C" void kernel_launch(void* const* d_in, const int* in_sizes, int n_in,
                              void* d_out, int out_size)
{
    const float* input  = (const float*)d_in[0];
    const float* pos    = (const float*)d_in[1];
    const float* memory = (const float*)d_in[2];
    const float* u      = (const float*)d_in[3];
    const float* v      = (const float*)d_in[4];
    const float* Wkv    = (const float*)d_in[5];
    const float* Wq     = (const float*)d_in[6];
    const float* Wp     = (const float*)d_in[7];
    const float* Wout   = (const float*)d_in[8];
    float* out = (float*)d_out;

    float *pq, *pp, *pawv;
    cudaGetSymbolAddress((void**)&pq,   g_q);
    cudaGetSymbolAddress((void**)&pp,   g_p);
    cudaGetSymbolAddress((void**)&pawv, g_awv);

    // kv = [memory; input] @ W_kv       (8192 x 2048 x 1024)
    mm_kv_tf32<<<dim3(16, 64), 256>>>(input, memory, Wkv);
    // q = input @ W_q                   (4096 x 1024 x 1024)
    mm_plain_tf32<<<dim3(8, 32), 256>>>(input, Wq, pq, BSZ * CS, H * D, DIN);
    // p = pos_embs @ W_p                (2048 x 1024 x 1024)
    mm_plain_tf32<<<dim3(8, 16), 256>>>(pos, Wp, pp, T, H * D, DIN);
    // pos_attn per head                 (16 x 4096 x 2048 x 64)
    mm_pa_tf32<<<dim3(16, 32, H), 256>>>(v);
    // fused flash attention with rel-shift gather
    attn_kernel<<<dim3(CS / 32, H, BSZ), 256>>>(u);
    // out = awv @ W_out                 (4096 x 1024 x 1024)
    mm_plain_tf32<<<dim3(8, 32), 256>>>(pawv, Wout, out, BSZ * CS, DIN, H * D);
}

// round 3
// speedup vs baseline: 3.7090x; 2.7660x over previous
#include <cuda_runtime.h>
#include <cstdint>

#define BSZ 4
#define CS  1024
#define PS  1024
#define DIN 1024
#define H   16
#define D   64
#define T   2048
#define SCALEF 0.125f

// ---------------- scratch (static device globals; allocation-free) ----------
__device__ float g_kv [(size_t)BSZ * T * 2 * H * D];   // [b*T+t][2048]  k: 0..1023, v: 1024..2047
__device__ float g_q  [(size_t)BSZ * CS * H * D];      // [b*CS+i][1024]
__device__ float g_p  [(size_t)T * H * D];             // [j][1024]
__device__ float g_pa [(size_t)H * BSZ * CS * T];      // [h][M][j]  pre-shift position scores
__device__ float g_awv[(size_t)BSZ * CS * H * D];      // attention output before W_out

// ---------------- tf32 helpers ----------------------------------------------
__device__ __forceinline__ uint32_t f2tf(float x) {
    uint32_t u;
    asm("cvt.rna.tf32.f32 %0, %1;" : "=r"(u) : "f"(x));
    return u;
}

#define MMA_TF32(c, a, b) \
    asm volatile("mma.sync.aligned.m16n8k8.row.col.f32.tf32.tf32.f32 " \
                 "{%0,%1,%2,%3},{%4,%5,%6,%7},{%8,%9},{%0,%1,%2,%3};" \
                 : "+f"(c[0]), "+f"(c[1]), "+f"(c[2]), "+f"(c[3]) \
                 : "r"(a[0]), "r"(a[1]), "r"(a[2]), "r"(a[3]), "r"(b[0]), "r"(b[1]))

#define AS_LD 36
#define BS_LD 136

// One K-chunk (32) of compute for this warp. acc[mt][nt][4].
__device__ __forceinline__ void mma_chunk(float acc[4][4][4],
                                          const uint32_t* __restrict__ As,
                                          const uint32_t* __restrict__ Bs,
                                          int wm, int wn, int lane)
{
    int g = lane >> 2, t = lane & 3;
#pragma unroll
    for (int ks = 0; ks < 4; ks++) {
        uint32_t a[4][4];
#pragma unroll
        for (int mt = 0; mt < 4; mt++) {
            int row = wm * 64 + mt * 16 + g;
            int col = ks * 8 + t;
            a[mt][0] = As[row * AS_LD + col];
            a[mt][1] = As[(row + 8) * AS_LD + col];
            a[mt][2] = As[row * AS_LD + col + 4];
            a[mt][3] = As[(row + 8) * AS_LD + col + 4];
        }
        uint32_t b[4][2];
#pragma unroll
        for (int nt = 0; nt < 4; nt++) {
            int brow = ks * 8 + t;
            int bcol = wn * 32 + nt * 8 + g;
            b[nt][0] = Bs[brow * BS_LD + bcol];
            b[nt][1] = Bs[(brow + 4) * BS_LD + bcol];
        }
#pragma unroll
        for (int mt = 0; mt < 4; mt++)
#pragma unroll
            for (int nt = 0; nt < 4; nt++)
                MMA_TF32(acc[mt][nt], a[mt], b[nt]);
    }
}

__device__ __forceinline__ void store_C(float acc[4][4][4], float* C, int ldc,
                                        int m0, int n0, int wm, int wn, int lane)
{
    int g = lane >> 2, t = lane & 3;
#pragma unroll
    for (int mt = 0; mt < 4; mt++) {
#pragma unroll
        for (int nt = 0; nt < 4; nt++) {
            int row = m0 + wm * 64 + mt * 16 + g;
            int col = n0 + wn * 32 + nt * 8 + 2 * t;
            float2 v01 = make_float2(acc[mt][nt][0], acc[mt][nt][1]);
            float2 v23 = make_float2(acc[mt][nt][2], acc[mt][nt][3]);
            *(float2*)(C + (size_t)row * ldc + col) = v01;
            *(float2*)(C + (size_t)(row + 8) * ldc + col) = v23;
        }
    }
}

__device__ __forceinline__ void stage_A_plain(uint32_t* As, const float* __restrict__ A,
                                              int lda, int m0, int k0, int tid)
{
#pragma unroll
    for (int i = 0; i < 4; i++) {
        int idx = tid + i * 256;
        int m = idx >> 3, kq = (idx & 7) * 4;
        float4 v = *(const float4*)(A + (size_t)(m0 + m) * lda + k0 + kq);
        As[m * AS_LD + kq + 0] = f2tf(v.x);
        As[m * AS_LD + kq + 1] = f2tf(v.y);
        As[m * AS_LD + kq + 2] = f2tf(v.z);
        As[m * AS_LD + kq + 3] = f2tf(v.w);
    }
}

__device__ __forceinline__ void stage_B_w(uint32_t* Bs, const float* __restrict__ B,
                                          int ldb, int k0, int n0, int tid)
{
#pragma unroll
    for (int i = 0; i < 4; i++) {
        int idx = tid + i * 256;
        int k = idx >> 5, n4 = (idx & 31) * 4;
        float4 v = *(const float4*)(B + (size_t)(k0 + k) * ldb + n0 + n4);
        Bs[k * BS_LD + n4 + 0] = f2tf(v.x);
        Bs[k * BS_LD + n4 + 1] = f2tf(v.y);
        Bs[k * BS_LD + n4 + 2] = f2tf(v.z);
        Bs[k * BS_LD + n4 + 3] = f2tf(v.w);
    }
}

// ---------------- plain GEMM: C = A @ B (tf32 tensor cores) -----------------
__global__ __launch_bounds__(256, 2)
void mm_plain_tf32(const float* __restrict__ A, const float* __restrict__ B,
                   float* __restrict__ C, int M, int N, int K)
{
    __shared__ uint32_t As[128 * AS_LD];
    __shared__ uint32_t Bs[32 * BS_LD];
    int tid = threadIdx.x, lane = tid & 31, w = tid >> 5;
    int wm = w >> 2, wn = w & 3;
    int m0 = blockIdx.y * 128, n0 = blockIdx.x * 128;

    float acc[4][4][4];
#pragma unroll
    for (int i = 0; i < 4; i++)
#pragma unroll
        for (int j = 0; j < 4; j++)
#pragma unroll
            for (int r = 0; r < 4; r++) acc[i][j][r] = 0.f;

    for (int k0 = 0; k0 < K; k0 += 32) {
        stage_A_plain(As, A, K, m0, k0, tid);
        stage_B_w(Bs, B, N, k0, n0, tid);
        __syncthreads();
        mma_chunk(acc, As, Bs, wm, wn, lane);
        __syncthreads();
    }
    store_C(acc, C, N, m0, n0, wm, wn, lane);
}

// ---------------- kv GEMM: A rows gathered from [memory; input] -------------
__global__ __launch_bounds__(256, 2)
void mm_kv_tf32(const float* __restrict__ input, const float* __restrict__ memory,
                const float* __restrict__ Wkv)
{
    const int N = 2 * H * D, K = DIN;
    __shared__ uint32_t As[128 * AS_LD];
    __shared__ uint32_t Bs[32 * BS_LD];
    int tid = threadIdx.x, lane = tid & 31, w = tid >> 5;
    int wm = w >> 2, wn = w & 3;
    int m0 = blockIdx.y * 128, n0 = blockIdx.x * 128;

    float acc[4][4][4];
#pragma unroll
    for (int i = 0; i < 4; i++)
#pragma unroll
        for (int j = 0; j < 4; j++)
#pragma unroll
            for (int r = 0; r < 4; r++) acc[i][j][r] = 0.f;

    for (int k0 = 0; k0 < K; k0 += 32) {
#pragma unroll
        for (int i = 0; i < 4; i++) {
            int idx = tid + i * 256;
            int m = idx >> 3, kq = (idx & 7) * 4;
            int grow = m0 + m;
            int b = grow >> 11;
            int tl = grow & (T - 1);
            const float* Arow = (tl < PS) ? (memory + (size_t)(b * PS + tl) * DIN)
                                          : (input + (size_t)(b * CS + (tl - PS)) * DIN);
            float4 v = *(const float4*)(Arow + k0 + kq);
            As[m * AS_LD + kq + 0] = f2tf(v.x);
            As[m * AS_LD + kq + 1] = f2tf(v.y);
            As[m * AS_LD + kq + 2] = f2tf(v.z);
            As[m * AS_LD + kq + 3] = f2tf(v.w);
        }
        stage_B_w(Bs, Wkv, N, k0, n0, tid);
        __syncthreads();
        mma_chunk(acc, As, Bs, wm, wn, lane);
        __syncthreads();
    }
    store_C(acc, g_kv, N, m0, n0, wm, wn, lane);
}

// ---------------- position-attn GEMM (per head) ------------------------------
__global__ __launch_bounds__(256, 2)
void mm_pa_tf32(const float* __restrict__ vvec)
{
    __shared__ uint32_t As[128 * AS_LD];
    __shared__ uint32_t Bs[32 * BS_LD];
    int tid = threadIdx.x, lane = tid & 31, w = tid >> 5;
    int wm = w >> 2, wn = w & 3;
    int h = blockIdx.z;
    int m0 = blockIdx.y * 128, n0 = blockIdx.x * 128;

    float acc[4][4][4];
#pragma unroll
    for (int i = 0; i < 4; i++)
#pragma unroll
        for (int j = 0; j < 4; j++)
#pragma unroll
            for (int r = 0; r < 4; r++) acc[i][j][r] = 0.f;

    for (int k0 = 0; k0 < D; k0 += 32) {
#pragma unroll
        for (int i = 0; i < 4; i++) {
            int idx = tid + i * 256;
            int m = idx >> 3, kq = (idx & 7) * 4;
            float4 a = *(const float4*)(g_q + (size_t)(m0 + m) * (H * D) + h * D + k0 + kq);
            float4 vv = *(const float4*)(vvec + h * D + k0 + kq);
            As[m * AS_LD + kq + 0] = f2tf(a.x + vv.x);
            As[m * AS_LD + kq + 1] = f2tf(a.y + vv.y);
            As[m * AS_LD + kq + 2] = f2tf(a.z + vv.z);
            As[m * AS_LD + kq + 3] = f2tf(a.w + vv.w);
        }
#pragma unroll
        for (int i = 0; i < 4; i++) {
            int idx = tid + i * 256;
            int n = idx & 127, k4 = (idx >> 7) * 4;
            float4 s = *(const float4*)(g_p + (size_t)(n0 + n) * (H * D) + h * D + k0 + k4);
            Bs[(k4 + 0) * BS_LD + n] = f2tf(s.x);
            Bs[(k4 + 1) * BS_LD + n] = f2tf(s.y);
            Bs[(k4 + 2) * BS_LD + n] = f2tf(s.z);
            Bs[(k4 + 3) * BS_LD + n] = f2tf(s.w);
        }
        __syncthreads();
        mma_chunk(acc, As, Bs, wm, wn, lane);
        __syncthreads();
    }
    store_C(acc, g_pa + (size_t)h * (BSZ * CS) * T, T, m0, n0, wm, wn, lane);
}

// ---------------- tensor-core flash attention with rel-shift gather ---------
#define AT_LD 68

__device__ __forceinline__ float pos_val(int h, int Mrow, int j) {
    int sp = j + BSZ * CS - Mrow;                       // in [1, 6143]
    int add = (sp >= (T + 1)) + (sp >= 2 * (T + 1));
    int Mp = Mrow + add;
    int jp = sp - add * (T + 1);
    return (jp == 0) ? 0.f
           : __ldg(&g_pa[((size_t)h * (BSZ * CS) + Mp) * T + (jp - 1)]);
}

// Bq=128 (8 warps x 16 rows), Bk=64. grid: (8, H, BSZ), 256 threads.
__global__ __launch_bounds__(256, 2)
void attn_tc(const float* __restrict__ u)
{
    extern __shared__ uint32_t sm[];
    uint32_t* Ks = sm;                    // 64 x AT_LD
    uint32_t* Vs = sm + 64 * AT_LD;       // 64 x AT_LD
    uint32_t* Ps = sm + 128 * AT_LD;      // 128 x AT_LD (also Q staging)

    int tid = threadIdx.x, lane = tid & 31, w = tid >> 5;
    int b = blockIdx.z, h = blockIdx.y;
    int q0 = (int)(gridDim.x - 1 - blockIdx.x) * 128;   // longest blocks first
    int g = lane >> 2, t = lane & 3;

    // stage Q(+u) into Ps as tf32
    for (int i = tid; i < 128 * 16; i += 256) {
        int r = i >> 4, c4 = (i & 15) * 4;
        float4 qv = *(const float4*)(g_q + (size_t)(b * CS + q0 + r) * (H * D) + h * D + c4);
        float4 uv = *(const float4*)(u + h * D + c4);
        Ps[r * AT_LD + c4 + 0] = f2tf(qv.x + uv.x);
        Ps[r * AT_LD + c4 + 1] = f2tf(qv.y + uv.y);
        Ps[r * AT_LD + c4 + 2] = f2tf(qv.z + uv.z);
        Ps[r * AT_LD + c4 + 3] = f2tf(qv.w + uv.w);
    }
    __syncthreads();

    uint32_t qf[8][4];
    {
        int r0 = w * 16 + g;
#pragma unroll
        for (int ks = 0; ks < 8; ks++) {
            qf[ks][0] = Ps[r0 * AT_LD + ks * 8 + t];
            qf[ks][1] = Ps[(r0 + 8) * AT_LD + ks * 8 + t];
            qf[ks][2] = Ps[r0 * AT_LD + ks * 8 + t + 4];
            qf[ks][3] = Ps[(r0 + 8) * AT_LD + ks * 8 + t + 4];
        }
    }

    float of[8][4];
#pragma unroll
    for (int nt = 0; nt < 8; nt++)
#pragma unroll
        for (int r = 0; r < 4; r++) of[nt][r] = 0.f;
    float m0r = -1e30f, m1r = -1e30f, l0 = 0.f, l1 = 0.f;

    int iq_g    = q0 + w * 16 + g;
    int Mrow_g  = b * CS + iq_g;
    int Mrow_g8 = Mrow_g + 8;
    int pr0 = (w * 16 + g) * AT_LD;
    int pr8 = (w * 16 + g + 8) * AT_LD;

    int ntiles = q0 / 64 + 18;

    for (int tt = 0; tt < ntiles; tt++) {
        int j0 = tt * 64;
        __syncthreads();
        // load K,V tile -> smem (tf32)
        for (int i = tid; i < 64 * 16; i += 256) {
            int r = i >> 4, c4 = (i & 15) * 4;
            const float* kvrow = g_kv + (size_t)(b * T + j0 + r) * (2 * H * D) + h * D;
            float4 k4 = *(const float4*)(kvrow + c4);
            float4 v4 = *(const float4*)(kvrow + H * D + c4);
            Ks[r * AT_LD + c4 + 0] = f2tf(k4.x);
            Ks[r * AT_LD + c4 + 1] = f2tf(k4.y);
            Ks[r * AT_LD + c4 + 2] = f2tf(k4.z);
            Ks[r * AT_LD + c4 + 3] = f2tf(k4.w);
            Vs[r * AT_LD + c4 + 0] = f2tf(v4.x);
            Vs[r * AT_LD + c4 + 1] = f2tf(v4.y);
            Vs[r * AT_LD + c4 + 2] = f2tf(v4.z);
            Vs[r * AT_LD + c4 + 3] = f2tf(v4.w);
        }
        __syncthreads();

        // S = (Q+u) K^T  (16 x 64 per warp)
        float sf[8][4];
#pragma unroll
        for (int nt = 0; nt < 8; nt++) {
            sf[nt][0] = sf[nt][1] = sf[nt][2] = sf[nt][3] = 0.f;
#pragma unroll
            for (int ks = 0; ks < 8; ks++) {
                uint32_t bb[2];
                bb[0] = Ks[(nt * 8 + g) * AT_LD + ks * 8 + t];
                bb[1] = Ks[(nt * 8 + g) * AT_LD + ks * 8 + t + 4];
                MMA_TF32(sf[nt], qf[ks], bb);
            }
        }

        // pos gather + scale + mask (mask only in last two tiles)
        bool need_mask = (tt >= ntiles - 2);
#pragma unroll
        for (int nt = 0; nt < 8; nt++) {
            int j = j0 + nt * 8 + 2 * t;
            sf[nt][0] = (sf[nt][0] + pos_val(h, Mrow_g,  j))     * SCALEF;
            sf[nt][1] = (sf[nt][1] + pos_val(h, Mrow_g,  j + 1)) * SCALEF;
            sf[nt][2] = (sf[nt][2] + pos_val(h, Mrow_g8, j))     * SCALEF;
            sf[nt][3] = (sf[nt][3] + pos_val(h, Mrow_g8, j + 1)) * SCALEF;
            if (need_mask) {
                int lim0 = iq_g + PS, lim1 = lim0 + 8;
                if (j     > lim0) sf[nt][0] = -1e30f;
                if (j + 1 > lim0) sf[nt][1] = -1e30f;
                if (j     > lim1) sf[nt][2] = -1e30f;
                if (j + 1 > lim1) sf[nt][3] = -1e30f;
            }
        }

        // online softmax (rows g, g+8 of this warp's 16)
        float tm0 = -1e30f, tm1 = -1e30f;
#pragma unroll
        for (int nt = 0; nt < 8; nt++) {
            tm0 = fmaxf(tm0, fmaxf(sf[nt][0], sf[nt][1]));
            tm1 = fmaxf(tm1, fmaxf(sf[nt][2], sf[nt][3]));
        }
        tm0 = fmaxf(tm0, __shfl_xor_sync(0xffffffffu, tm0, 1));
        tm0 = fmaxf(tm0, __shfl_xor_sync(0xffffffffu, tm0, 2));
        tm1 = fmaxf(tm1, __shfl_xor_sync(0xffffffffu, tm1, 1));
        tm1 = fmaxf(tm1, __shfl_xor_sync(0xffffffffu, tm1, 2));
        float nm0 = fmaxf(m0r, tm0), nm1 = fmaxf(m1r, tm1);
        float cr0 = __expf(m0r - nm0), cr1 = __expf(m1r - nm1);

        float ps0 = 0.f, ps1 = 0.f;
#pragma unroll
        for (int nt = 0; nt < 8; nt++) {
            float e0 = __expf(sf[nt][0] - nm0);
            float e1 = __expf(sf[nt][1] - nm0);
            float e2 = __expf(sf[nt][2] - nm1);
            float e3 = __expf(sf[nt][3] - nm1);
            int col = nt * 8 + 2 * t;
            Ps[pr0 + col]     = f2tf(e0);
            Ps[pr0 + col + 1] = f2tf(e1);
            Ps[pr8 + col]     = f2tf(e2);
            Ps[pr8 + col + 1] = f2tf(e3);
            ps0 += e0 + e1;
            ps1 += e2 + e3;
        }
        ps0 += __shfl_xor_sync(0xffffffffu, ps0, 1);
        ps0 += __shfl_xor_sync(0xffffffffu, ps0, 2);
        ps1 += __shfl_xor_sync(0xffffffffu, ps1, 1);
        ps1 += __shfl_xor_sync(0xffffffffu, ps1, 2);
        l0 = l0 * cr0 + ps0;
        l1 = l1 * cr1 + ps1;
        m0r = nm0; m1r = nm1;
#pragma unroll
        for (int nt = 0; nt < 8; nt++) {
            of[nt][0] *= cr0; of[nt][1] *= cr0;
            of[nt][2] *= cr1; of[nt][3] *= cr1;
        }
        __syncwarp();

        // O += P @ V
        uint32_t af[8][4];
#pragma unroll
        for (int ks = 0; ks < 8; ks++) {
            af[ks][0] = Ps[pr0 + ks * 8 + t];
            af[ks][1] = Ps[pr8 + ks * 8 + t];
            af[ks][2] = Ps[pr0 + ks * 8 + t + 4];
            af[ks][3] = Ps[pr8 + ks * 8 + t + 4];
        }
#pragma unroll
        for (int nt = 0; nt < 8; nt++) {
#pragma unroll
            for (int ks = 0; ks < 8; ks++) {
                uint32_t bb[2];
                bb[0] = Vs[(ks * 8 + t) * AT_LD + nt * 8 + g];
                bb[1] = Vs[(ks * 8 + t + 4) * AT_LD + nt * 8 + g];
                MMA_TF32(of[nt], af[ks], bb);
            }
        }
        __syncwarp();
    }

    float i0 = 1.f / l0, i1 = 1.f / l1;
    int orow = b * CS + q0 + w * 16 + g;
#pragma unroll
    for (int nt = 0; nt < 8; nt++) {
        int col = h * D + nt * 8 + 2 * t;
        *(float2*)(g_awv + (size_t)orow * (H * D) + col) =
            make_float2(of[nt][0] * i0, of[nt][1] * i0);
        *(float2*)(g_awv + (size_t)(orow + 8) * (H * D) + col) =
            make_float2(of[nt][2] * i1, of[nt][3] * i1);
    }
}

// ---------------- launch -----------------------------------------------------
extern "C" void kernel_launch(void* const* d_in, const int* in_sizes, int n_in,
                              void* d_out, int out_size)
{
    const float* input  = (const float*)d_in[0];
    const float* pos    = (const float*)d_in[1];
    const float* memory = (const float*)d_in[2];
    const float* u      = (const float*)d_in[3];
    const float* v      = (const float*)d_in[4];
    const float* Wkv    = (const float*)d_in[5];
    const float* Wq     = (const float*)d_in[6];
    const float* Wp     = (const float*)d_in[7];
    const float* Wout   = (const float*)d_in[8];
    float* out = (float*)d_out;

    float *pq, *pp, *pawv;
    cudaGetSymbolAddress((void**)&pq,   g_q);
    cudaGetSymbolAddress((void**)&pp,   g_p);
    cudaGetSymbolAddress((void**)&pawv, g_awv);

    const int ATT_SMEM = 256 * AT_LD * 4;   // 69632 B
    cudaFuncSetAttribute(attn_tc, cudaFuncAttributeMaxDynamicSharedMemorySize, ATT_SMEM);

    // kv = [memory; input] @ W_kv       (8192 x 2048 x 1024)
    mm_kv_tf32<<<dim3(16, 64), 256>>>(input, memory, Wkv);
    // q = input @ W_q                   (4096 x 1024 x 1024)
    mm_plain_tf32<<<dim3(8, 32), 256>>>(input, Wq, pq, BSZ * CS, H * D, DIN);
    // p = pos_embs @ W_p                (2048 x 1024 x 1024)
    mm_plain_tf32<<<dim3(8, 16), 256>>>(pos, Wp, pp, T, H * D, DIN);
    // pos_attn per head                 (16 x 4096 x 2048 x 64)
    mm_pa_tf32<<<dim3(16, 32, H), 256>>>(v);
    // tensor-core flash attention with rel-shift gather
    attn_tc<<<dim3(8, H, BSZ), 256, ATT_SMEM>>>(u);
    // out = awv @ W_out                 (4096 x 1024 x 1024)
    mm_plain_tf32<<<dim3(8, 32), 256>>>(pawv, Wout, out, BSZ * CS, DIN, H * D);
}

// round 4
// speedup vs baseline: 3.8855x; 1.0476x over previous
#include <cuda_runtime.h>
#include <cstdint>

#define BSZ 4
#define CS  1024
#define PS  1024
#define DIN 1024
#define H   16
#define D   64
#define T   2048
#define SCALEF 0.125f

// ---------------- scratch (static device globals; allocation-free) ----------
__device__ float g_kv [(size_t)BSZ * T * 2 * H * D];   // [b*T+t][2048]  k: 0..1023, v: 1024..2047
__device__ float g_q  [(size_t)BSZ * CS * H * D];      // [b*CS+i][1024]
__device__ float g_p  [(size_t)T * H * D];             // [j][1024]
__device__ float g_pa [(size_t)H * BSZ * CS * T];      // [h][M][j]  pre-shift position scores
__device__ float g_awv[(size_t)BSZ * CS * H * D];      // attention output (tf32-rounded)

// tf32-rounded copies of GEMM sources (pre-round pass)
__device__ float r_input[(size_t)BSZ * CS * DIN];
__device__ float r_mem  [(size_t)BSZ * PS * DIN];
__device__ float r_pos  [(size_t)T * DIN];
__device__ float r_wkv  [(size_t)DIN * 2 * H * D];
__device__ float r_wq   [(size_t)DIN * H * D];
__device__ float r_wp   [(size_t)DIN * H * D];
__device__ float r_wout [(size_t)H * D * DIN];

// ---------------- tf32 helpers ----------------------------------------------
__device__ __forceinline__ uint32_t f2tf(float x) {
    uint32_t u;
    asm("cvt.rna.tf32.f32 %0, %1;" : "=r"(u) : "f"(x));
    return u;
}

#define MMA_TF32(c, a, b) \
    asm volatile("mma.sync.aligned.m16n8k8.row.col.f32.tf32.tf32.f32 " \
                 "{%0,%1,%2,%3},{%4,%5,%6,%7},{%8,%9},{%0,%1,%2,%3};" \
                 : "+f"(c[0]), "+f"(c[1]), "+f"(c[2]), "+f"(c[3]) \
                 : "r"(a[0]), "r"(a[1]), "r"(a[2]), "r"(a[3]), "r"(b[0]), "r"(b[1]))

__device__ __forceinline__ void cp16(uint32_t* smem_dst, const float* gmem_src) {
    uint32_t sa = (uint32_t)__cvta_generic_to_shared(smem_dst);
    asm volatile("cp.async.cg.shared.global [%0], [%1], 16;" :: "r"(sa), "l"(gmem_src));
}
#define CP_COMMIT asm volatile("cp.async.commit_group;")
#define CP_WAIT1  asm volatile("cp.async.wait_group 1;")

#define AS_LD 36
#define BS_LD 136
#define STAGE_SZ (128 * AS_LD + 32 * BS_LD)   // 8960 words per pipeline stage

// ---------------- elementwise tf32 rounding pass ------------------------------
__global__ void round_tf32(const float* __restrict__ src, float* __restrict__ dst, int n4)
{
    int i = blockIdx.x * blockDim.x + threadIdx.x;
    if (i < n4) {
        float4 v = *(const float4*)(src + i * 4);
        uint4 r;
        r.x = f2tf(v.x); r.y = f2tf(v.y); r.z = f2tf(v.z); r.w = f2tf(v.w);
        *(uint4*)(dst + i * 4) = r;
    }
}

// ---------------- shared MMA compute / epilogue ------------------------------
__device__ __forceinline__ void mma_chunk(float acc[4][4][4],
                                          const uint32_t* __restrict__ As,
                                          const uint32_t* __restrict__ Bs,
                                          int wm, int wn, int lane)
{
    int g = lane >> 2, t = lane & 3;
#pragma unroll
    for (int ks = 0; ks < 4; ks++) {
        uint32_t a[4][4];
#pragma unroll
        for (int mt = 0; mt < 4; mt++) {
            int row = wm * 64 + mt * 16 + g;
            int col = ks * 8 + t;
            a[mt][0] = As[row * AS_LD + col];
            a[mt][1] = As[(row + 8) * AS_LD + col];
            a[mt][2] = As[row * AS_LD + col + 4];
            a[mt][3] = As[(row + 8) * AS_LD + col + 4];
        }
        uint32_t b[4][2];
#pragma unroll
        for (int nt = 0; nt < 4; nt++) {
            int brow = ks * 8 + t;
            int bcol = wn * 32 + nt * 8 + g;
            b[nt][0] = Bs[brow * BS_LD + bcol];
            b[nt][1] = Bs[(brow + 4) * BS_LD + bcol];
        }
#pragma unroll
        for (int mt = 0; mt < 4; mt++)
#pragma unroll
            for (int nt = 0; nt < 4; nt++)
                MMA_TF32(acc[mt][nt], a[mt], b[nt]);
    }
}

__device__ __forceinline__ void store_C(float acc[4][4][4], float* C, int ldc,
                                        int m0, int n0, int wm, int wn, int lane)
{
    int g = lane >> 2, t = lane & 3;
#pragma unroll
    for (int mt = 0; mt < 4; mt++) {
#pragma unroll
        for (int nt = 0; nt < 4; nt++) {
            int row = m0 + wm * 64 + mt * 16 + g;
            int col = n0 + wn * 32 + nt * 8 + 2 * t;
            float2 v01 = make_float2(acc[mt][nt][0], acc[mt][nt][1]);
            float2 v23 = make_float2(acc[mt][nt][2], acc[mt][nt][3]);
            *(float2*)(C + (size_t)row * ldc + col) = v01;
            *(float2*)(C + (size_t)(row + 8) * ldc + col) = v23;
        }
    }
}

// ---------------- cp.async staging -------------------------------------------
__device__ __forceinline__ void stage_AB(uint32_t* As, uint32_t* Bs,
                                         const float* __restrict__ A, int lda,
                                         const float* __restrict__ B, int ldb,
                                         int m0, int n0, int k0, int tid)
{
#pragma unroll
    for (int i = 0; i < 4; i++) {
        int s = tid + i * 256;
        int row = s >> 3, kq = (s & 7) * 4;
        cp16(&As[row * AS_LD + kq], A + (size_t)(m0 + row) * lda + k0 + kq);
    }
#pragma unroll
    for (int i = 0; i < 4; i++) {
        int s = tid + i * 256;
        int k = s >> 5, n4 = (s & 31) * 4;
        cp16(&Bs[k * BS_LD + n4], B + (size_t)(k0 + k) * ldb + n0 + n4);
    }
}

// ---------------- pipelined plain GEMM: C = A @ B ----------------------------
__global__ __launch_bounds__(256, 2)
void mm_ca(const float* __restrict__ A, const float* __restrict__ B,
           float* __restrict__ C, int M, int N, int K)
{
    extern __shared__ uint32_t dsm[];
    int tid = threadIdx.x, lane = tid & 31, w = tid >> 5;
    int wm = w >> 2, wn = w & 3;
    int m0 = blockIdx.y * 128, n0 = blockIdx.x * 128;

    float acc[4][4][4];
#pragma unroll
    for (int i = 0; i < 4; i++)
#pragma unroll
        for (int j = 0; j < 4; j++)
#pragma unroll
            for (int r = 0; r < 4; r++) acc[i][j][r] = 0.f;

    uint32_t* As[2] = { dsm, dsm + STAGE_SZ };
    uint32_t* Bs[2] = { dsm + 128 * AS_LD, dsm + STAGE_SZ + 128 * AS_LD };

    stage_AB(As[0], Bs[0], A, K, B, N, m0, n0, 0, tid);  CP_COMMIT;
    stage_AB(As[1], Bs[1], A, K, B, N, m0, n0, 32, tid); CP_COMMIT;
    CP_WAIT1;
    __syncthreads();

    int NK = K >> 5;
    for (int k = 0; k < NK; k++) {
        int cur = k & 1;
        mma_chunk(acc, As[cur], Bs[cur], wm, wn, lane);
        __syncthreads();
        if (k + 2 < NK)
            stage_AB(As[cur], Bs[cur], A, K, B, N, m0, n0, (k + 2) * 32, tid);
        CP_COMMIT;
        CP_WAIT1;
        __syncthreads();
    }
    store_C(acc, C, N, m0, n0, wm, wn, lane);
}

// ---------------- pipelined kv GEMM: A gathered from [memory; input] ---------
__device__ __forceinline__ void stage_A_kv(uint32_t* As, int m0, int k0, int tid)
{
#pragma unroll
    for (int i = 0; i < 4; i++) {
        int s = tid + i * 256;
        int row = s >> 3, kq = (s & 7) * 4;
        int grow = m0 + row;
        int b = grow >> 11;
        int tl = grow & (T - 1);
        const float* Arow = (tl < PS) ? (r_mem + (size_t)(b * PS + tl) * DIN)
                                      : (r_input + (size_t)(b * CS + (tl - PS)) * DIN);
        cp16(&As[row * AS_LD + kq], Arow + k0 + kq);
    }
}

__device__ __forceinline__ void stage_B_kv(uint32_t* Bs, int n0, int k0, int tid)
{
#pragma unroll
    for (int i = 0; i < 4; i++) {
        int s = tid + i * 256;
        int k = s >> 5, n4 = (s & 31) * 4;
        cp16(&Bs[k * BS_LD + n4], r_wkv + (size_t)(k0 + k) * (2 * H * D) + n0 + n4);
    }
}

__global__ __launch_bounds__(256, 2)
void mm_ca_kv()
{
    extern __shared__ uint32_t dsm[];
    int tid = threadIdx.x, lane = tid & 31, w = tid >> 5;
    int wm = w >> 2, wn = w & 3;
    int m0 = blockIdx.y * 128, n0 = blockIdx.x * 128;

    float acc[4][4][4];
#pragma unroll
    for (int i = 0; i < 4; i++)
#pragma unroll
        for (int j = 0; j < 4; j++)
#pragma unroll
            for (int r = 0; r < 4; r++) acc[i][j][r] = 0.f;

    uint32_t* As[2] = { dsm, dsm + STAGE_SZ };
    uint32_t* Bs[2] = { dsm + 128 * AS_LD, dsm + STAGE_SZ + 128 * AS_LD };

    stage_A_kv(As[0], m0, 0, tid);  stage_B_kv(Bs[0], n0, 0, tid);  CP_COMMIT;
    stage_A_kv(As[1], m0, 32, tid); stage_B_kv(Bs[1], n0, 32, tid); CP_COMMIT;
    CP_WAIT1;
    __syncthreads();

    const int NK = DIN >> 5;
    for (int k = 0; k < NK; k++) {
        int cur = k & 1;
        mma_chunk(acc, As[cur], Bs[cur], wm, wn, lane);
        __syncthreads();
        if (k + 2 < NK) {
            stage_A_kv(As[cur], m0, (k + 2) * 32, tid);
            stage_B_kv(Bs[cur], n0, (k + 2) * 32, tid);
        }
        CP_COMMIT;
        CP_WAIT1;
        __syncthreads();
    }
    store_C(acc, g_kv, 2 * H * D, m0, n0, wm, wn, lane);
}

// ---------------- position-attn GEMM (per head), register staging ------------
__global__ __launch_bounds__(256, 2)
void mm_pa_tf32(const float* __restrict__ vvec)
{
    __shared__ uint32_t As[128 * AS_LD];
    __shared__ uint32_t Bs[32 * BS_LD];
    int tid = threadIdx.x, lane = tid & 31, w = tid >> 5;
    int wm = w >> 2, wn = w & 3;
    int h = blockIdx.z;
    int m0 = blockIdx.y * 128, n0 = blockIdx.x * 128;

    float acc[4][4][4];
#pragma unroll
    for (int i = 0; i < 4; i++)
#pragma unroll
        for (int j = 0; j < 4; j++)
#pragma unroll
            for (int r = 0; r < 4; r++) acc[i][j][r] = 0.f;

    for (int k0 = 0; k0 < D; k0 += 32) {
#pragma unroll
        for (int i = 0; i < 4; i++) {
            int idx = tid + i * 256;
            int m = idx >> 3, kq = (idx & 7) * 4;
            float4 a = *(const float4*)(g_q + (size_t)(m0 + m) * (H * D) + h * D + k0 + kq);
            float4 vv = *(const float4*)(vvec + h * D + k0 + kq);
            As[m * AS_LD + kq + 0] = f2tf(a.x + vv.x);
            As[m * AS_LD + kq + 1] = f2tf(a.y + vv.y);
            As[m * AS_LD + kq + 2] = f2tf(a.z + vv.z);
            As[m * AS_LD + kq + 3] = f2tf(a.w + vv.w);
        }
#pragma unroll
        for (int i = 0; i < 4; i++) {
            int idx = tid + i * 256;
            int n = idx & 127, k4 = (idx >> 7) * 4;
            float4 s = *(const float4*)(g_p + (size_t)(n0 + n) * (H * D) + h * D + k0 + k4);
            Bs[(k4 + 0) * BS_LD + n] = f2tf(s.x);
            Bs[(k4 + 1) * BS_LD + n] = f2tf(s.y);
            Bs[(k4 + 2) * BS_LD + n] = f2tf(s.z);
            Bs[(k4 + 3) * BS_LD + n] = f2tf(s.w);
        }
        __syncthreads();
        mma_chunk(acc, As, Bs, wm, wn, lane);
        __syncthreads();
    }
    store_C(acc, g_pa + (size_t)h * (BSZ * CS) * T, T, m0, n0, wm, wn, lane);
}

// ---------------- tensor-core flash attention with rel-shift gather ----------
#define AT_LD 68

__device__ __forceinline__ float pos_val(int h, int Mrow, int j) {
    int sp = j + BSZ * CS - Mrow;                       // in [1, 6143]
    int add = (sp >= (T + 1)) + (sp >= 2 * (T + 1));
    int Mp = Mrow + add;
    int jp = sp - add * (T + 1);
    return (jp == 0) ? 0.f
           : __ldg(&g_pa[((size_t)h * (BSZ * CS) + Mp) * T + (jp - 1)]);
}

__global__ __launch_bounds__(256, 2)
void attn_tc(const float* __restrict__ u)
{
    extern __shared__ uint32_t sm[];
    uint32_t* Ks = sm;                    // 64 x AT_LD
    uint32_t* Vs = sm + 64 * AT_LD;       // 64 x AT_LD
    uint32_t* Ps = sm + 128 * AT_LD;      // 128 x AT_LD (also Q staging)

    int tid = threadIdx.x, lane = tid & 31, w = tid >> 5;
    int b = blockIdx.z, h = blockIdx.y;
    int q0 = (int)(gridDim.x - 1 - blockIdx.x) * 128;
    int g = lane >> 2, t = lane & 3;

    for (int i = tid; i < 128 * 16; i += 256) {
        int r = i >> 4, c4 = (i & 15) * 4;
        float4 qv = *(const float4*)(g_q + (size_t)(b * CS + q0 + r) * (H * D) + h * D + c4);
        float4 uv = *(const float4*)(u + h * D + c4);
        Ps[r * AT_LD + c4 + 0] = f2tf(qv.x + uv.x);
        Ps[r * AT_LD + c4 + 1] = f2tf(qv.y + uv.y);
        Ps[r * AT_LD + c4 + 2] = f2tf(qv.z + uv.z);
        Ps[r * AT_LD + c4 + 3] = f2tf(qv.w + uv.w);
    }
    __syncthreads();

    uint32_t qf[8][4];
    {
        int r0 = w * 16 + g;
#pragma unroll
        for (int ks = 0; ks < 8; ks++) {
            qf[ks][0] = Ps[r0 * AT_LD + ks * 8 + t];
            qf[ks][1] = Ps[(r0 + 8) * AT_LD + ks * 8 + t];
            qf[ks][2] = Ps[r0 * AT_LD + ks * 8 + t + 4];
            qf[ks][3] = Ps[(r0 + 8) * AT_LD + ks * 8 + t + 4];
        }
    }

    float of[8][4];
#pragma unroll
    for (int nt = 0; nt < 8; nt++)
#pragma unroll
        for (int r = 0; r < 4; r++) of[nt][r] = 0.f;
    float m0r = -1e30f, m1r = -1e30f, l0 = 0.f, l1 = 0.f;

    int iq_g    = q0 + w * 16 + g;
    int Mrow_g  = b * CS + iq_g;
    int Mrow_g8 = Mrow_g + 8;
    int pr0 = (w * 16 + g) * AT_LD;
    int pr8 = (w * 16 + g + 8) * AT_LD;

    int ntiles = q0 / 64 + 18;

    for (int tt = 0; tt < ntiles; tt++) {
        int j0 = tt * 64;
        __syncthreads();
        for (int i = tid; i < 64 * 16; i += 256) {
            int r = i >> 4, c4 = (i & 15) * 4;
            const float* kvrow = g_kv + (size_t)(b * T + j0 + r) * (2 * H * D) + h * D;
            float4 k4 = *(const float4*)(kvrow + c4);
            float4 v4 = *(const float4*)(kvrow + H * D + c4);
            Ks[r * AT_LD + c4 + 0] = f2tf(k4.x);
            Ks[r * AT_LD + c4 + 1] = f2tf(k4.y);
            Ks[r * AT_LD + c4 + 2] = f2tf(k4.z);
            Ks[r * AT_LD + c4 + 3] = f2tf(k4.w);
            Vs[r * AT_LD + c4 + 0] = f2tf(v4.x);
            Vs[r * AT_LD + c4 + 1] = f2tf(v4.y);
            Vs[r * AT_LD + c4 + 2] = f2tf(v4.z);
            Vs[r * AT_LD + c4 + 3] = f2tf(v4.w);
        }
        __syncthreads();

        float sf[8][4];
#pragma unroll
        for (int nt = 0; nt < 8; nt++) {
            sf[nt][0] = sf[nt][1] = sf[nt][2] = sf[nt][3] = 0.f;
#pragma unroll
            for (int ks = 0; ks < 8; ks++) {
                uint32_t bb[2];
                bb[0] = Ks[(nt * 8 + g) * AT_LD + ks * 8 + t];
                bb[1] = Ks[(nt * 8 + g) * AT_LD + ks * 8 + t + 4];
                MMA_TF32(sf[nt], qf[ks], bb);
            }
        }

        bool need_mask = (tt >= ntiles - 2);
#pragma unroll
        for (int nt = 0; nt < 8; nt++) {
            int j = j0 + nt * 8 + 2 * t;
            sf[nt][0] = (sf[nt][0] + pos_val(h, Mrow_g,  j))     * SCALEF;
            sf[nt][1] = (sf[nt][1] + pos_val(h, Mrow_g,  j + 1)) * SCALEF;
            sf[nt][2] = (sf[nt][2] + pos_val(h, Mrow_g8, j))     * SCALEF;
            sf[nt][3] = (sf[nt][3] + pos_val(h, Mrow_g8, j + 1)) * SCALEF;
            if (need_mask) {
                int lim0 = iq_g + PS, lim1 = lim0 + 8;
                if (j     > lim0) sf[nt][0] = -1e30f;
                if (j + 1 > lim0) sf[nt][1] = -1e30f;
                if (j     > lim1) sf[nt][2] = -1e30f;
                if (j + 1 > lim1) sf[nt][3] = -1e30f;
            }
        }

        float tm0 = -1e30f, tm1 = -1e30f;
#pragma unroll
        for (int nt = 0; nt < 8; nt++) {
            tm0 = fmaxf(tm0, fmaxf(sf[nt][0], sf[nt][1]));
            tm1 = fmaxf(tm1, fmaxf(sf[nt][2], sf[nt][3]));
        }
        tm0 = fmaxf(tm0, __shfl_xor_sync(0xffffffffu, tm0, 1));
        tm0 = fmaxf(tm0, __shfl_xor_sync(0xffffffffu, tm0, 2));
        tm1 = fmaxf(tm1, __shfl_xor_sync(0xffffffffu, tm1, 1));
        tm1 = fmaxf(tm1, __shfl_xor_sync(0xffffffffu, tm1, 2));
        float nm0 = fmaxf(m0r, tm0), nm1 = fmaxf(m1r, tm1);
        float cr0 = __expf(m0r - nm0), cr1 = __expf(m1r - nm1);

        float ps0 = 0.f, ps1 = 0.f;
#pragma unroll
        for (int nt = 0; nt < 8; nt++) {
            float e0 = __expf(sf[nt][0] - nm0);
            float e1 = __expf(sf[nt][1] - nm0);
            float e2 = __expf(sf[nt][2] - nm1);
            float e3 = __expf(sf[nt][3] - nm1);
            int col = nt * 8 + 2 * t;
            Ps[pr0 + col]     = f2tf(e0);
            Ps[pr0 + col + 1] = f2tf(e1);
            Ps[pr8 + col]     = f2tf(e2);
            Ps[pr8 + col + 1] = f2tf(e3);
            ps0 += e0 + e1;
            ps1 += e2 + e3;
        }
        ps0 += __shfl_xor_sync(0xffffffffu, ps0, 1);
        ps0 += __shfl_xor_sync(0xffffffffu, ps0, 2);
        ps1 += __shfl_xor_sync(0xffffffffu, ps1, 1);
        ps1 += __shfl_xor_sync(0xffffffffu, ps1, 2);
        l0 = l0 * cr0 + ps0;
        l1 = l1 * cr1 + ps1;
        m0r = nm0; m1r = nm1;
#pragma unroll
        for (int nt = 0; nt < 8; nt++) {
            of[nt][0] *= cr0; of[nt][1] *= cr0;
            of[nt][2] *= cr1; of[nt][3] *= cr1;
        }
        __syncwarp();

        uint32_t af[8][4];
#pragma unroll
        for (int ks = 0; ks < 8; ks++) {
            af[ks][0] = Ps[pr0 + ks * 8 + t];
            af[ks][1] = Ps[pr8 + ks * 8 + t];
            af[ks][2] = Ps[pr0 + ks * 8 + t + 4];
            af[ks][3] = Ps[pr8 + ks * 8 + t + 4];
        }
#pragma unroll
        for (int nt = 0; nt < 8; nt++) {
#pragma unroll
            for (int ks = 0; ks < 8; ks++) {
                uint32_t bb[2];
                bb[0] = Vs[(ks * 8 + t) * AT_LD + nt * 8 + g];
                bb[1] = Vs[(ks * 8 + t + 4) * AT_LD + nt * 8 + g];
                MMA_TF32(of[nt], af[ks], bb);
            }
        }
        __syncwarp();
    }

    float i0 = 1.f / l0, i1 = 1.f / l1;
    int orow = b * CS + q0 + w * 16 + g;
#pragma unroll
    for (int nt = 0; nt < 8; nt++) {
        int col = h * D + nt * 8 + 2 * t;
        // tf32-round the epilogue so mm_ca (W_out) can consume via raw cp.async
        float2 v0 = make_float2(__uint_as_float(f2tf(of[nt][0] * i0)),
                                __uint_as_float(f2tf(of[nt][1] * i0)));
        float2 v1 = make_float2(__uint_as_float(f2tf(of[nt][2] * i1)),
                                __uint_as_float(f2tf(of[nt][3] * i1)));
        *(float2*)(g_awv + (size_t)orow * (H * D) + col) = v0;
        *(float2*)(g_awv + (size_t)(orow + 8) * (H * D) + col) = v1;
    }
}

// ---------------- launch -----------------------------------------------------
extern "C" void kernel_launch(void* const* d_in, const int* in_sizes, int n_in,
                              void* d_out, int out_size)
{
    const float* input  = (const float*)d_in[0];
    const float* pos    = (const float*)d_in[1];
    const float* memory = (const float*)d_in[2];
    const float* u      = (const float*)d_in[3];
    const float* v      = (const float*)d_in[4];
    const float* Wkv    = (const float*)d_in[5];
    const float* Wq     = (const float*)d_in[6];
    const float* Wp     = (const float*)d_in[7];
    const float* Wout   = (const float*)d_in[8];
    float* out = (float*)d_out;

    float *pq, *pp, *pawv;
    float *pri, *prm, *prp, *prkv, *prq, *prwp, *prwo;
    cudaGetSymbolAddress((void**)&pq,   g_q);
    cudaGetSymbolAddress((void**)&pp,   g_p);
    cudaGetSymbolAddress((void**)&pawv, g_awv);
    cudaGetSymbolAddress((void**)&pri,  r_input);
    cudaGetSymbolAddress((void**)&prm,  r_mem);
    cudaGetSymbolAddress((void**)&prp,  r_pos);
    cudaGetSymbolAddress((void**)&prkv, r_wkv);
    cudaGetSymbolAddress((void**)&prq,  r_wq);
    cudaGetSymbolAddress((void**)&prwp, r_wp);
    cudaGetSymbolAddress((void**)&prwo, r_wout);

    const int MM_SMEM  = 2 * STAGE_SZ * 4;   // 71680 B
    const int ATT_SMEM = 256 * AT_LD * 4;    // 69632 B
    cudaFuncSetAttribute(mm_ca,    cudaFuncAttributeMaxDynamicSharedMemorySize, MM_SMEM);
    cudaFuncSetAttribute(mm_ca_kv, cudaFuncAttributeMaxDynamicSharedMemorySize, MM_SMEM);
    cudaFuncSetAttribute(attn_tc,  cudaFuncAttributeMaxDynamicSharedMemorySize, ATT_SMEM);

    // pre-round GEMM sources to tf32-clean fp32
    auto rr = [](const float* s, float* d, int n) {
        round_tf32<<<(n / 4 + 255) / 256, 256>>>(s, d, n / 4);
    };
    rr(input,  pri,  BSZ * CS * DIN);
    rr(memory, prm,  BSZ * PS * DIN);
    rr(pos,    prp,  T * DIN);
    rr(Wkv,    prkv, DIN * 2 * H * D);
    rr(Wq,     prq,  DIN * H * D);
    rr(Wp,     prwp, DIN * H * D);
    rr(Wout,   prwo, H * D * DIN);

    // kv = [memory; input] @ W_kv       (8192 x 2048 x 1024)
    mm_ca_kv<<<dim3(16, 64), 256, MM_SMEM>>>();
    // q = input @ W_q                   (4096 x 1024 x 1024)
    mm_ca<<<dim3(8, 32), 256, MM_SMEM>>>(pri, prq, pq, BSZ * CS, H * D, DIN);
    // p = pos_embs @ W_p                (2048 x 1024 x 1024)
    mm_ca<<<dim3(8, 16), 256, MM_SMEM>>>(prp, prwp, pp, T, H * D, DIN);
    // pos_attn per head                 (16 x 4096 x 2048 x 64)
    mm_pa_tf32<<<dim3(16, 32, H), 256>>>(v);
    // tensor-core flash attention with rel-shift gather
    attn_tc<<<dim3(8, H, BSZ), 256, ATT_SMEM>>>(u);
    // out = awv @ W_out                 (4096 x 1024 x 1024)
    mm_ca<<<dim3(8, 32), 256, MM_SMEM>>>(pawv, prwo, out, BSZ * CS, DIN, H * D);
}

// round 5
// speedup vs baseline: 3.9035x; 1.0046x over previous
#include <cuda_runtime.h>
#include <cstdint>

#define BSZ 4
#define CS  1024
#define PS  1024
#define DIN 1024
#define H   16
#define D   64
#define T   2048
#define SCALEF 0.125f

// ---------------- scratch (static device globals; allocation-free) ----------
__device__ float g_kv [(size_t)BSZ * T * 2 * H * D];   // [b*T+t][2048]  k: 0..1023, v: 1024..2047
__device__ float g_q  [(size_t)BSZ * CS * H * D];      // [b*CS+i][1024]
__device__ float g_p  [(size_t)T * H * D];             // [j][1024]
__device__ float g_pa [(size_t)H * BSZ * CS * T];      // [h][M][j]  pre-shift position scores
__device__ float g_awv[(size_t)BSZ * CS * H * D];      // attention output (tf32-rounded)

// tf32-rounded copies of GEMM sources (pre-round pass)
__device__ float r_input[(size_t)BSZ * CS * DIN];
__device__ float r_mem  [(size_t)BSZ * PS * DIN];
__device__ float r_pos  [(size_t)T * DIN];
__device__ float r_wkv  [(size_t)DIN * 2 * H * D];
__device__ float r_wq   [(size_t)DIN * H * D];
__device__ float r_wp   [(size_t)DIN * H * D];
__device__ float r_wout [(size_t)H * D * DIN];

// ---------------- tf32 helpers ----------------------------------------------
__device__ __forceinline__ uint32_t f2tf(float x) {
    uint32_t u;
    asm("cvt.rna.tf32.f32 %0, %1;" : "=r"(u) : "f"(x));
    return u;
}

#define MMA_TF32(c, a, b) \
    asm volatile("mma.sync.aligned.m16n8k8.row.col.f32.tf32.tf32.f32 " \
                 "{%0,%1,%2,%3},{%4,%5,%6,%7},{%8,%9},{%0,%1,%2,%3};" \
                 : "+f"(c[0]), "+f"(c[1]), "+f"(c[2]), "+f"(c[3]) \
                 : "r"(a[0]), "r"(a[1]), "r"(a[2]), "r"(a[3]), "r"(b[0]), "r"(b[1]))

__device__ __forceinline__ void cp16(uint32_t* smem_dst, const float* gmem_src) {
    uint32_t sa = (uint32_t)__cvta_generic_to_shared(smem_dst);
    asm volatile("cp.async.cg.shared.global [%0], [%1], 16;" :: "r"(sa), "l"(gmem_src));
}
#define CP_COMMIT asm volatile("cp.async.commit_group;")
#define CP_WAIT1  asm volatile("cp.async.wait_group 1;")

#define AS_LD 36
#define BS_LD 136
#define STAGE_SZ (128 * AS_LD + 32 * BS_LD)   // 8960 words per pipeline stage

// ---------------- elementwise tf32 rounding pass ------------------------------
__global__ void round_tf32(const float* __restrict__ src, float* __restrict__ dst, int n4)
{
    int i = blockIdx.x * blockDim.x + threadIdx.x;
    if (i < n4) {
        float4 v = *(const float4*)(src + i * 4);
        uint4 r;
        r.x = f2tf(v.x); r.y = f2tf(v.y); r.z = f2tf(v.z); r.w = f2tf(v.w);
        *(uint4*)(dst + i * 4) = r;
    }
}

// ---------------- shared MMA compute / epilogue ------------------------------
__device__ __forceinline__ void mma_chunk(float acc[4][4][4],
                                          const uint32_t* __restrict__ As,
                                          const uint32_t* __restrict__ Bs,
                                          int wm, int wn, int lane)
{
    int g = lane >> 2, t = lane & 3;
#pragma unroll
    for (int ks = 0; ks < 4; ks++) {
        uint32_t a[4][4];
#pragma unroll
        for (int mt = 0; mt < 4; mt++) {
            int row = wm * 64 + mt * 16 + g;
            int col = ks * 8 + t;
            a[mt][0] = As[row * AS_LD + col];
            a[mt][1] = As[(row + 8) * AS_LD + col];
            a[mt][2] = As[row * AS_LD + col + 4];
            a[mt][3] = As[(row + 8) * AS_LD + col + 4];
        }
        uint32_t b[4][2];
#pragma unroll
        for (int nt = 0; nt < 4; nt++) {
            int brow = ks * 8 + t;
            int bcol = wn * 32 + nt * 8 + g;
            b[nt][0] = Bs[brow * BS_LD + bcol];
            b[nt][1] = Bs[(brow + 4) * BS_LD + bcol];
        }
#pragma unroll
        for (int mt = 0; mt < 4; mt++)
#pragma unroll
            for (int nt = 0; nt < 4; nt++)
                MMA_TF32(acc[mt][nt], a[mt], b[nt]);
    }
}

__device__ __forceinline__ void store_C(float acc[4][4][4], float* C, int ldc,
                                        int m0, int n0, int wm, int wn, int lane)
{
    int g = lane >> 2, t = lane & 3;
#pragma unroll
    for (int mt = 0; mt < 4; mt++) {
#pragma unroll
        for (int nt = 0; nt < 4; nt++) {
            int row = m0 + wm * 64 + mt * 16 + g;
            int col = n0 + wn * 32 + nt * 8 + 2 * t;
            float2 v01 = make_float2(acc[mt][nt][0], acc[mt][nt][1]);
            float2 v23 = make_float2(acc[mt][nt][2], acc[mt][nt][3]);
            *(float2*)(C + (size_t)row * ldc + col) = v01;
            *(float2*)(C + (size_t)(row + 8) * ldc + col) = v23;
        }
    }
}

// ---------------- cp.async staging -------------------------------------------
__device__ __forceinline__ void stage_AB(uint32_t* As, uint32_t* Bs,
                                         const float* __restrict__ A, int lda,
                                         const float* __restrict__ B, int ldb,
                                         int m0, int n0, int k0, int tid)
{
#pragma unroll
    for (int i = 0; i < 4; i++) {
        int s = tid + i * 256;
        int row = s >> 3, kq = (s & 7) * 4;
        cp16(&As[row * AS_LD + kq], A + (size_t)(m0 + row) * lda + k0 + kq);
    }
#pragma unroll
    for (int i = 0; i < 4; i++) {
        int s = tid + i * 256;
        int k = s >> 5, n4 = (s & 31) * 4;
        cp16(&Bs[k * BS_LD + n4], B + (size_t)(k0 + k) * ldb + n0 + n4);
    }
}

// ---------------- pipelined plain GEMM: C = A @ B ----------------------------
__global__ __launch_bounds__(256, 2)
void mm_ca(const float* __restrict__ A, const float* __restrict__ B,
           float* __restrict__ C, int M, int N, int K)
{
    extern __shared__ uint32_t dsm[];
    int tid = threadIdx.x, lane = tid & 31, w = tid >> 5;
    int wm = w >> 2, wn = w & 3;
    int m0 = blockIdx.y * 128, n0 = blockIdx.x * 128;

    float acc[4][4][4];
#pragma unroll
    for (int i = 0; i < 4; i++)
#pragma unroll
        for (int j = 0; j < 4; j++)
#pragma unroll
            for (int r = 0; r < 4; r++) acc[i][j][r] = 0.f;

    uint32_t* As[2] = { dsm, dsm + STAGE_SZ };
    uint32_t* Bs[2] = { dsm + 128 * AS_LD, dsm + STAGE_SZ + 128 * AS_LD };

    stage_AB(As[0], Bs[0], A, K, B, N, m0, n0, 0, tid);  CP_COMMIT;
    stage_AB(As[1], Bs[1], A, K, B, N, m0, n0, 32, tid); CP_COMMIT;
    CP_WAIT1;
    __syncthreads();

    int NK = K >> 5;
    for (int k = 0; k < NK; k++) {
        int cur = k & 1;
        mma_chunk(acc, As[cur], Bs[cur], wm, wn, lane);
        __syncthreads();
        if (k + 2 < NK)
            stage_AB(As[cur], Bs[cur], A, K, B, N, m0, n0, (k + 2) * 32, tid);
        CP_COMMIT;
        CP_WAIT1;
        __syncthreads();
    }
    store_C(acc, C, N, m0, n0, wm, wn, lane);
}

// ---------------- pipelined kv GEMM: A gathered from [memory; input] ---------
__device__ __forceinline__ void stage_A_kv(uint32_t* As, int m0, int k0, int tid)
{
#pragma unroll
    for (int i = 0; i < 4; i++) {
        int s = tid + i * 256;
        int row = s >> 3, kq = (s & 7) * 4;
        int grow = m0 + row;
        int b = grow >> 11;
        int tl = grow & (T - 1);
        const float* Arow = (tl < PS) ? (r_mem + (size_t)(b * PS + tl) * DIN)
                                      : (r_input + (size_t)(b * CS + (tl - PS)) * DIN);
        cp16(&As[row * AS_LD + kq], Arow + k0 + kq);
    }
}

__device__ __forceinline__ void stage_B_kv(uint32_t* Bs, int n0, int k0, int tid)
{
#pragma unroll
    for (int i = 0; i < 4; i++) {
        int s = tid + i * 256;
        int k = s >> 5, n4 = (s & 31) * 4;
        cp16(&Bs[k * BS_LD + n4], r_wkv + (size_t)(k0 + k) * (2 * H * D) + n0 + n4);
    }
}

__global__ __launch_bounds__(256, 2)
void mm_ca_kv()
{
    extern __shared__ uint32_t dsm[];
    int tid = threadIdx.x, lane = tid & 31, w = tid >> 5;
    int wm = w >> 2, wn = w & 3;
    int m0 = blockIdx.y * 128, n0 = blockIdx.x * 128;

    float acc[4][4][4];
#pragma unroll
    for (int i = 0; i < 4; i++)
#pragma unroll
        for (int j = 0; j < 4; j++)
#pragma unroll
            for (int r = 0; r < 4; r++) acc[i][j][r] = 0.f;

    uint32_t* As[2] = { dsm, dsm + STAGE_SZ };
    uint32_t* Bs[2] = { dsm + 128 * AS_LD, dsm + STAGE_SZ + 128 * AS_LD };

    stage_A_kv(As[0], m0, 0, tid);  stage_B_kv(Bs[0], n0, 0, tid);  CP_COMMIT;
    stage_A_kv(As[1], m0, 32, tid); stage_B_kv(Bs[1], n0, 32, tid); CP_COMMIT;
    CP_WAIT1;
    __syncthreads();

    const int NK = DIN >> 5;
    for (int k = 0; k < NK; k++) {
        int cur = k & 1;
        mma_chunk(acc, As[cur], Bs[cur], wm, wn, lane);
        __syncthreads();
        if (k + 2 < NK) {
            stage_A_kv(As[cur], m0, (k + 2) * 32, tid);
            stage_B_kv(Bs[cur], n0, (k + 2) * 32, tid);
        }
        CP_COMMIT;
        CP_WAIT1;
        __syncthreads();
    }
    store_C(acc, g_kv, 2 * H * D, m0, n0, wm, wn, lane);
}

// ---------------- position-attn GEMM (per head), register staging ------------
__global__ __launch_bounds__(256, 2)
void mm_pa_tf32(const float* __restrict__ vvec)
{
    __shared__ uint32_t As[128 * AS_LD];
    __shared__ uint32_t Bs[32 * BS_LD];
    int tid = threadIdx.x, lane = tid & 31, w = tid >> 5;
    int wm = w >> 2, wn = w & 3;
    int h = blockIdx.z;
    int m0 = blockIdx.y * 128, n0 = blockIdx.x * 128;

    float acc[4][4][4];
#pragma unroll
    for (int i = 0; i < 4; i++)
#pragma unroll
        for (int j = 0; j < 4; j++)
#pragma unroll
            for (int r = 0; r < 4; r++) acc[i][j][r] = 0.f;

    for (int k0 = 0; k0 < D; k0 += 32) {
#pragma unroll
        for (int i = 0; i < 4; i++) {
            int idx = tid + i * 256;
            int m = idx >> 3, kq = (idx & 7) * 4;
            float4 a = *(const float4*)(g_q + (size_t)(m0 + m) * (H * D) + h * D + k0 + kq);
            float4 vv = *(const float4*)(vvec + h * D + k0 + kq);
            As[m * AS_LD + kq + 0] = f2tf(a.x + vv.x);
            As[m * AS_LD + kq + 1] = f2tf(a.y + vv.y);
            As[m * AS_LD + kq + 2] = f2tf(a.z + vv.z);
            As[m * AS_LD + kq + 3] = f2tf(a.w + vv.w);
        }
#pragma unroll
        for (int i = 0; i < 4; i++) {
            int idx = tid + i * 256;
            int n = idx & 127, k4 = (idx >> 7) * 4;
            float4 s = *(const float4*)(g_p + (size_t)(n0 + n) * (H * D) + h * D + k0 + k4);
            Bs[(k4 + 0) * BS_LD + n] = f2tf(s.x);
            Bs[(k4 + 1) * BS_LD + n] = f2tf(s.y);
            Bs[(k4 + 2) * BS_LD + n] = f2tf(s.z);
            Bs[(k4 + 3) * BS_LD + n] = f2tf(s.w);
        }
        __syncthreads();
        mma_chunk(acc, As, Bs, wm, wn, lane);
        __syncthreads();
    }
    store_C(acc, g_pa + (size_t)h * (BSZ * CS) * T, T, m0, n0, wm, wn, lane);
}

// ---------------- tensor-core flash attention with rel-shift gather ----------
#define AT_LD 68

__device__ __forceinline__ float pos_val(int h, int Mrow, int j) {
    int sp = j + BSZ * CS - Mrow;                       // in [1, 6143]
    int add = (sp >= (T + 1)) + (sp >= 2 * (T + 1));
    int Mp = Mrow + add;
    int jp = sp - add * (T + 1);
    return (jp == 0) ? 0.f
           : __ldg(&g_pa[((size_t)h * (BSZ * CS) + Mp) * T + (jp - 1)]);
}

__global__ __launch_bounds__(256, 2)
void attn_tc(const float* __restrict__ u)
{
    extern __shared__ uint32_t sm[];
    uint32_t* Ks = sm;                    // 64 x AT_LD
    uint32_t* Vs = sm + 64 * AT_LD;       // 64 x AT_LD
    uint32_t* Ps = sm + 128 * AT_LD;      // 128 x AT_LD (also Q staging)

    int tid = threadIdx.x, lane = tid & 31, w = tid >> 5;
    int b = blockIdx.z, h = blockIdx.y;
    int q0 = (int)(gridDim.x - 1 - blockIdx.x) * 128;
    int g = lane >> 2, t = lane & 3;

    for (int i = tid; i < 128 * 16; i += 256) {
        int r = i >> 4, c4 = (i & 15) * 4;
        float4 qv = *(const float4*)(g_q + (size_t)(b * CS + q0 + r) * (H * D) + h * D + c4);
        float4 uv = *(const float4*)(u + h * D + c4);
        Ps[r * AT_LD + c4 + 0] = f2tf(qv.x + uv.x);
        Ps[r * AT_LD + c4 + 1] = f2tf(qv.y + uv.y);
        Ps[r * AT_LD + c4 + 2] = f2tf(qv.z + uv.z);
        Ps[r * AT_LD + c4 + 3] = f2tf(qv.w + uv.w);
    }
    __syncthreads();

    uint32_t qf[8][4];
    {
        int r0 = w * 16 + g;
#pragma unroll
        for (int ks = 0; ks < 8; ks++) {
            qf[ks][0] = Ps[r0 * AT_LD + ks * 8 + t];
            qf[ks][1] = Ps[(r0 + 8) * AT_LD + ks * 8 + t];
            qf[ks][2] = Ps[r0 * AT_LD + ks * 8 + t + 4];
            qf[ks][3] = Ps[(r0 + 8) * AT_LD + ks * 8 + t + 4];
        }
    }

    float of[8][4];
#pragma unroll
    for (int nt = 0; nt < 8; nt++)
#pragma unroll
        for (int r = 0; r < 4; r++) of[nt][r] = 0.f;
    float m0r = -1e30f, m1r = -1e30f, l0 = 0.f, l1 = 0.f;

    int iq_g    = q0 + w * 16 + g;
    int Mrow_g  = b * CS + iq_g;
    int Mrow_g8 = Mrow_g + 8;
    int pr0 = (w * 16 + g) * AT_LD;
    int pr8 = (w * 16 + g + 8) * AT_LD;

    int ntiles = q0 / 64 + 18;

    for (int tt = 0; tt < ntiles; tt++) {
        int j0 = tt * 64;
        __syncthreads();
        for (int i = tid; i < 64 * 16; i += 256) {
            int r = i >> 4, c4 = (i & 15) * 4;
            const float* kvrow = g_kv + (size_t)(b * T + j0 + r) * (2 * H * D) + h * D;
            float4 k4 = *(const float4*)(kvrow + c4);
            float4 v4 = *(const float4*)(kvrow + H * D + c4);
            Ks[r * AT_LD + c4 + 0] = f2tf(k4.x);
            Ks[r * AT_LD + c4 + 1] = f2tf(k4.y);
            Ks[r * AT_LD + c4 + 2] = f2tf(k4.z);
            Ks[r * AT_LD + c4 + 3] = f2tf(k4.w);
            Vs[r * AT_LD + c4 + 0] = f2tf(v4.x);
            Vs[r * AT_LD + c4 + 1] = f2tf(v4.y);
            Vs[r * AT_LD + c4 + 2] = f2tf(v4.z);
            Vs[r * AT_LD + c4 + 3] = f2tf(v4.w);
        }
        __syncthreads();

        float sf[8][4];
#pragma unroll
        for (int nt = 0; nt < 8; nt++) {
            sf[nt][0] = sf[nt][1] = sf[nt][2] = sf[nt][3] = 0.f;
#pragma unroll
            for (int ks = 0; ks < 8; ks++) {
                uint32_t bb[2];
                bb[0] = Ks[(nt * 8 + g) * AT_LD + ks * 8 + t];
                bb[1] = Ks[(nt * 8 + g) * AT_LD + ks * 8 + t + 4];
                MMA_TF32(sf[nt], qf[ks], bb);
            }
        }

        bool need_mask = (tt >= ntiles - 2);
#pragma unroll
        for (int nt = 0; nt < 8; nt++) {
            int j = j0 + nt * 8 + 2 * t;
            sf[nt][0] = (sf[nt][0] + pos_val(h, Mrow_g,  j))     * SCALEF;
            sf[nt][1] = (sf[nt][1] + pos_val(h, Mrow_g,  j + 1)) * SCALEF;
            sf[nt][2] = (sf[nt][2] + pos_val(h, Mrow_g8, j))     * SCALEF;
            sf[nt][3] = (sf[nt][3] + pos_val(h, Mrow_g8, j + 1)) * SCALEF;
            if (need_mask) {
                int lim0 = iq_g + PS, lim1 = lim0 + 8;
                if (j     > lim0) sf[nt][0] = -1e30f;
                if (j + 1 > lim0) sf[nt][1] = -1e30f;
                if (j     > lim1) sf[nt][2] = -1e30f;
                if (j + 1 > lim1) sf[nt][3] = -1e30f;
            }
        }

        float tm0 = -1e30f, tm1 = -1e30f;
#pragma unroll
        for (int nt = 0; nt < 8; nt++) {
            tm0 = fmaxf(tm0, fmaxf(sf[nt][0], sf[nt][1]));
            tm1 = fmaxf(tm1, fmaxf(sf[nt][2], sf[nt][3]));
        }
        tm0 = fmaxf(tm0, __shfl_xor_sync(0xffffffffu, tm0, 1));
        tm0 = fmaxf(tm0, __shfl_xor_sync(0xffffffffu, tm0, 2));
        tm1 = fmaxf(tm1, __shfl_xor_sync(0xffffffffu, tm1, 1));
        tm1 = fmaxf(tm1, __shfl_xor_sync(0xffffffffu, tm1, 2));
        float nm0 = fmaxf(m0r, tm0), nm1 = fmaxf(m1r, tm1);
        float cr0 = __expf(m0r - nm0), cr1 = __expf(m1r - nm1);

        float ps0 = 0.f, ps1 = 0.f;
#pragma unroll
        for (int nt = 0; nt < 8; nt++) {
            float e0 = __expf(sf[nt][0] - nm0);
            float e1 = __expf(sf[nt][1] - nm0);
            float e2 = __expf(sf[nt][2] - nm1);
            float e3 = __expf(sf[nt][3] - nm1);
            int col = nt * 8 + 2 * t;
            Ps[pr0 + col]     = f2tf(e0);
            Ps[pr0 + col + 1] = f2tf(e1);
            Ps[pr8 + col]     = f2tf(e2);
            Ps[pr8 + col + 1] = f2tf(e3);
            ps0 += e0 + e1;
            ps1 += e2 + e3;
        }
        ps0 += __shfl_xor_sync(0xffffffffu, ps0, 1);
        ps0 += __shfl_xor_sync(0xffffffffu, ps0, 2);
        ps1 += __shfl_xor_sync(0xffffffffu, ps1, 1);
        ps1 += __shfl_xor_sync(0xffffffffu, ps1, 2);
        l0 = l0 * cr0 + ps0;
        l1 = l1 * cr1 + ps1;
        m0r = nm0; m1r = nm1;
#pragma unroll
        for (int nt = 0; nt < 8; nt++) {
            of[nt][0] *= cr0; of[nt][1] *= cr0;
            of[nt][2] *= cr1; of[nt][3] *= cr1;
        }
        __syncwarp();

        uint32_t af[8][4];
#pragma unroll
        for (int ks = 0; ks < 8; ks++) {
            af[ks][0] = Ps[pr0 + ks * 8 + t];
            af[ks][1] = Ps[pr8 + ks * 8 + t];
            af[ks][2] = Ps[pr0 + ks * 8 + t + 4];
            af[ks][3] = Ps[pr8 + ks * 8 + t + 4];
        }
#pragma unroll
        for (int nt = 0; nt < 8; nt++) {
#pragma unroll
            for (int ks = 0; ks < 8; ks++) {
                uint32_t bb[2];
                bb[0] = Vs[(ks * 8 + t) * AT_LD + nt * 8 + g];
                bb[1] = Vs[(ks * 8 + t + 4) * AT_LD + nt * 8 + g];
                MMA_TF32(of[nt], af[ks], bb);
            }
        }
        __syncwarp();
    }

    float i0 = 1.f / l0, i1 = 1.f / l1;
    int orow = b * CS + q0 + w * 16 + g;
#pragma unroll
    for (int nt = 0; nt < 8; nt++) {
        int col = h * D + nt * 8 + 2 * t;
        // tf32-round the epilogue so mm_ca (W_out) can consume via raw cp.async
        float2 v0 = make_float2(__uint_as_float(f2tf(of[nt][0] * i0)),
                                __uint_as_float(f2tf(of[nt][1] * i0)));
        float2 v1 = make_float2(__uint_as_float(f2tf(of[nt][2] * i1)),
                                __uint_as_float(f2tf(of[nt][3] * i1)));
        *(float2*)(g_awv + (size_t)orow * (H * D) + col) = v0;
        *(float2*)(g_awv + (size_t)(orow + 8) * (H * D) + col) = v1;
    }
}

// ---------------- launch -----------------------------------------------------
extern "C" void kernel_launch(void* const* d_in, const int* in_sizes, int n_in,
                              void* d_out, int out_size)
{
    const float* input  = (const float*)d_in[0];
    const float* pos    = (const float*)d_in[1];
    const float* memory = (const float*)d_in[2];
    const float* u      = (const float*)d_in[3];
    const float* v      = (const float*)d_in[4];
    const float* Wkv    = (const float*)d_in[5];
    const float* Wq     = (const float*)d_in[6];
    const float* Wp     = (const float*)d_in[7];
    const float* Wout   = (const float*)d_in[8];
    float* out = (float*)d_out;

    float *pq, *pp, *pawv;
    float *pri, *prm, *prp, *prkv, *prq, *prwp, *prwo;
    cudaGetSymbolAddress((void**)&pq,   g_q);
    cudaGetSymbolAddress((void**)&pp,   g_p);
    cudaGetSymbolAddress((void**)&pawv, g_awv);
    cudaGetSymbolAddress((void**)&pri,  r_input);
    cudaGetSymbolAddress((void**)&prm,  r_mem);
    cudaGetSymbolAddress((void**)&prp,  r_pos);
    cudaGetSymbolAddress((void**)&prkv, r_wkv);
    cudaGetSymbolAddress((void**)&prq,  r_wq);
    cudaGetSymbolAddress((void**)&prwp, r_wp);
    cudaGetSymbolAddress((void**)&prwo, r_wout);

    const int MM_SMEM  = 2 * STAGE_SZ * 4;   // 71680 B
    const int ATT_SMEM = 256 * AT_LD * 4;    // 69632 B
    cudaFuncSetAttribute(mm_ca,    cudaFuncAttributeMaxDynamicSharedMemorySize, MM_SMEM);
    cudaFuncSetAttribute(mm_ca_kv, cudaFuncAttributeMaxDynamicSharedMemorySize, MM_SMEM);
    cudaFuncSetAttribute(attn_tc,  cudaFuncAttributeMaxDynamicSharedMemorySize, ATT_SMEM);

    // pre-round GEMM sources to tf32-clean fp32
    auto rr = [](const float* s, float* d, int n) {
        round_tf32<<<(n / 4 + 255) / 256, 256>>>(s, d, n / 4);
    };
    rr(input,  pri,  BSZ * CS * DIN);
    rr(memory, prm,  BSZ * PS * DIN);
    rr(pos,    prp,  T * DIN);
    rr(Wkv,    prkv, DIN * 2 * H * D);
    rr(Wq,     prq,  DIN * H * D);
    rr(Wp,     prwp, DIN * H * D);
    rr(Wout,   prwo, H * D * DIN);

    // kv = [memory; input] @ W_kv       (8192 x 2048 x 1024)
    mm_ca_kv<<<dim3(16, 64), 256, MM_SMEM>>>();
    // q = input @ W_q                   (4096 x 1024 x 1024)
    mm_ca<<<dim3(8, 32), 256, MM_SMEM>>>(pri, prq, pq, BSZ * CS, H * D, DIN);
    // p = pos_embs @ W_p                (2048 x 1024 x 1024)
    mm_ca<<<dim3(8, 16), 256, MM_SMEM>>>(prp, prwp, pp, T, H * D, DIN);
    // pos_attn per head                 (16 x 4096 x 2048 x 64)
    mm_pa_tf32<<<dim3(16, 32, H), 256>>>(v);
    // tensor-core flash attention with rel-shift gather
    attn_tc<<<dim3(8, H, BSZ), 256, ATT_SMEM>>>(u);
    // out = awv @ W_out                 (4096 x 1024 x 1024)
    mm_ca<<<dim3(8, 32), 256, MM_SMEM>>>(pawv, prwo, out, BSZ * CS, DIN, H * D);
}